// round 14
// baseline (speedup 1.0000x reference)
#include <cuda_runtime.h>
#include <cuda_bf16.h>
#include <math.h>
#include <stdint.h>

// Shapes
#define Bsz 16
#define CH 64
#define H1 14
#define W1 254
#define HWp (H1*W1)            // 3556
#define CHWp (CH*HWp)          // 227584
#define Ncap 28448
#define Ecls 8
#define ODv 16

// padded NHWC planes for conv2 A operand: rows -2..16 (19), cols -2..261 (264)
#define PRows 19
#define PCols 264
#define PLANE_E ((size_t)Bsz*PRows*PCols*64)

// ---------------- scratch ----------------
__device__ float g_h1[Bsz*CHWp];
__device__ float g_y2[Bsz*CHWp];
__device__ float g_h3[Bsz*CHWp];
__device__ float g_u [Bsz*Ncap*8];
__device__ float g_s [3*2048];
__device__ float g_vsum[2048];
__device__ __nv_bfloat16 g_h1h[PLANE_E];
__device__ __nv_bfloat16 g_h1l[PLANE_E];
__device__ __nv_bfloat16 g_w2t[36*2*4096];   // [tap][hl][co][ci]

__global__ void zero_k() {
    int t = blockIdx.x*256 + threadIdx.x;
    if (t < 3*2048) g_s[t] = 0.f;
    if (t < 2048)   g_vsum[t] = 0.f;
}
// zero only the padding border of the NHWC planes (conv1 fills the interior)
__global__ void zerop_k() {
    int i = blockIdx.x*256 + threadIdx.x;   // 16 b x 1460 pos x 8 chunks
    if (i >= 16*1460*8) return;
    int c8 = i & 7; int r = i >> 3;
    int b = r / 1460; int p = r - b*1460;
    int row, col;
    if (p < 1320) { int rr = p/264; col = p - rr*264; row = rr < 2 ? rr : rr + 14; }
    else { int q = p - 1320; int rr = q/10; int cc = q - rr*10;
           row = 2 + rr; col = cc < 2 ? cc : cc + 254; }
    size_t off = (((size_t)b*PRows + row)*PCols + col)*64 + c8*8;
    uint4 z = make_uint4(0,0,0,0);
    *(uint4*)(g_h1h + off) = z;
    *(uint4*)(g_h1l + off) = z;
}

// ---------------- prep: transpose+split w2 -> [tap][hl][co][ci] bf16 ----
__global__ void splitw2_k(const float* __restrict__ w2) {
    int i = blockIdx.x*256 + threadIdx.x;
    if (i < 64*2304) {
        int co = i / 2304, r = i - co*2304;
        int ci = r / 36, tap = r - ci*36;
        float v = w2[i];
        __nv_bfloat16 h = __float2bfloat16(v);
        __nv_bfloat16 l = __float2bfloat16(v - __bfloat162float(h));
        g_w2t[(tap*2+0)*4096 + co*64 + ci] = h;
        g_w2t[(tap*2+1)*4096 + co*64 + ci] = l;
    }
}

// ---- conv1: 1->64ch 6x6 s2, relu; fp32 + NHWC bf16 hi/lo; 2 rows/block ----
__global__ void __launch_bounds__(512)
conv1_k(const float* __restrict__ x,
        const float* __restrict__ w1,
        const float* __restrict__ b1) {
    __shared__ float xs[8*512];
    __shared__ float ws[2304];
    __shared__ float bs[64];
    int h2 = blockIdx.x, b = blockIdx.y, t = threadIdx.x;
    const float* xrow = x + b*(32*512) + (4*h2)*512;   // rows 4h2..4h2+7
    for (int j = t; j < 4096; j += 512) xs[j] = xrow[j];
    for (int j = t; j < 2304; j += 512) ws[j] = w1[j];
    if (t < 64) bs[t] = b1[t];
    __syncthreads();
    int sub = t >> 8, tw = t & 255;
    if (tw >= W1) return;
    int h = h2*2 + sub;
    float win[36];
#pragma unroll
    for (int r = 0; r < 6; r++)
#pragma unroll
        for (int k = 0; k < 6; k++) win[r*6+k] = xs[(sub*2 + r)*512 + 2*tw + k];
    float* outp = g_h1 + (size_t)(b*CH*H1 + h)*W1 + tw;
    uint32_t* ph = (uint32_t*)(g_h1h + (((size_t)b*PRows + h+2)*PCols + tw+2)*64);
    uint32_t* pl = (uint32_t*)(g_h1l + (((size_t)b*PRows + h+2)*PCols + tw+2)*64);
    for (int f = 0; f < 64; f += 2) {
        float a0 = bs[f], a1 = bs[f+1];
        const float* wp0 = ws + f*36;
        const float* wp1 = wp0 + 36;
#pragma unroll
        for (int k = 0; k < 36; k++) {
            a0 = fmaf(win[k], wp0[k], a0);
            a1 = fmaf(win[k], wp1[k], a1);
        }
        a0 = fmaxf(a0, 0.f); a1 = fmaxf(a1, 0.f);
        outp[(size_t)f*HWp]     = a0;
        outp[(size_t)(f+1)*HWp] = a1;
        __nv_bfloat162 hv = __floats2bfloat162_rn(a0, a1);
        __nv_bfloat162 lv = __floats2bfloat162_rn(
            a0 - __bfloat162float(hv.x), a1 - __bfloat162float(hv.y));
        ph[f>>1] = *(uint32_t*)&hv;
        pl[f>>1] = *(uint32_t*)&lv;
    }
}

// ===== conv2: tap-decomposed GEMM, pure-cp.async staging, ldmatrix ======
#define AROWS 134
#define A_PB (AROWS*128)
#define B_PB (64*128)
#define C2S_A (4*A_PB)
#define C2S_B (4*B_PB)
#define C2_SMEM (C2S_A + C2S_B)

static __device__ __forceinline__ void mma16816(float* c,
    uint32_t a0, uint32_t a1, uint32_t a2, uint32_t a3,
    uint32_t b0, uint32_t b1) {
    asm volatile(
        "mma.sync.aligned.m16n8k16.row.col.f32.bf16.bf16.f32 "
        "{%0,%1,%2,%3}, {%4,%5,%6,%7}, {%8,%9}, {%0,%1,%2,%3};"
        : "+f"(c[0]), "+f"(c[1]), "+f"(c[2]), "+f"(c[3])
        : "r"(a0), "r"(a1), "r"(a2), "r"(a3), "r"(b0), "r"(b1));
}
static __device__ __forceinline__ void ldsm4(uint32_t& r0, uint32_t& r1,
    uint32_t& r2, uint32_t& r3, unsigned a) {
    asm volatile("ldmatrix.sync.aligned.m8n8.x4.shared.b16 {%0,%1,%2,%3}, [%4];"
        : "=r"(r0), "=r"(r1), "=r"(r2), "=r"(r3) : "r"(a));
}
__device__ __forceinline__ void cpa16g(unsigned d, const void* s) {
    asm volatile("cp.async.cg.shared.global [%0], [%1], 16;" :: "r"(d), "l"(s));
}

__global__ void __launch_bounds__(256, 2)
conv2_mma(const float* __restrict__ b2) {
    extern __shared__ char cs2[];
    unsigned sA, sB;
    { unsigned u; asm("{ .reg .u64 tp; cvta.to.shared.u64 tp, %1; cvt.u32.u64 %0, tp; }"
                      : "=r"(u) : "l"(cs2));
      sA = u; sB = u + C2S_A; }

    const int wt = blockIdx.x, h = blockIdx.y, b = blockIdx.z;
    const int t = threadIdx.x, lane = t & 31, wid = t >> 5;
    const int mbase = wid * 16;
    const int w0 = wt * 128;

    float acc[8][4];
#pragma unroll
    for (int nt = 0; nt < 8; nt++)
#pragma unroll
        for (int q = 0; q < 4; q++) acc[nt][q] = 0.f;

    auto stageA = [&](int kh, int buf) {
        const char* ph = (const char*)(g_h1h + (((size_t)b*PRows + h+kh)*PCols + w0)*64);
        const char* pl = (const char*)(g_h1l + (((size_t)b*PRows + h+kh)*PCols + w0)*64);
#pragma unroll
        for (int i = 0; i < 9; i++) {
            int idx = t + i*256;
            if (idx < 2144) {
                int hl = idx >= 1072;
                int r = idx - hl*1072;
                int pp = r >> 3, c = r & 7;
                cpa16g(sA + (unsigned)((buf*2+hl)*A_PB + pp*128 + ((c^(pp&7))*16)),
                       (hl ? pl : ph) + pp*128 + c*16);
            }
        }
        asm volatile("cp.async.commit_group;");
    };
    auto stageB = [&](int tap, int buf) {
#pragma unroll
        for (int i = 0; i < 4; i++) {
            int idx = t + i*256;
            int hl = idx >> 9;
            int r = idx & 511;
            int co = r >> 3, c = r & 7;
            cpa16g(sB + (unsigned)((buf*2+hl)*B_PB + co*128 + ((c^(co&7))*16)),
                   (const char*)(g_w2t + (size_t)(tap*2+hl)*4096 + co*64) + c*16);
        }
        asm volatile("cp.async.commit_group;");
    };

    stageA(0, 0);
    stageB(0, 0);
    stageB(1, 1);
    asm volatile("cp.async.wait_group 1;");
    __syncthreads();

    const int arsel = (lane & 7) + ((lane >> 3) & 1)*8;
    const int acsel = (lane >> 4) & 1;
    const int brsel = (lane & 7) + ((lane >> 4) & 1)*8;
    const int bcsel = (lane >> 3) & 1;

    for (int kh = 0; kh < 6; kh++) {
        const unsigned aHi = sA + (unsigned)(kh & 1)*2*A_PB;
#pragma unroll 1
        for (int kw = 0; kw < 6; kw++) {
            const int tap = kh*6 + kw;
            if (tap > 0) __syncthreads();
            if (tap >= 1 && tap + 1 <= 35) stageB(tap + 1, (tap + 1) & 1);
            if (kw == 4 && kh < 5) stageA(kh + 1, (kh + 1) & 1);
            asm volatile("cp.async.wait_group 1;");
            __syncthreads();

            const unsigned bHi = sB + (unsigned)(tap & 1)*2*B_PB;
            const int arow = mbase + kw + arsel;
            const unsigned aBase = aHi + (unsigned)(arow*128);
            const int axr = (arow & 7);
#pragma unroll
            for (int kf = 0; kf < 4; kf++) {
                int ac = kf*2 + acsel;
                unsigned aaddr = aBase + (unsigned)(((ac ^ axr))*16);
                uint32_t ah0,ah1,ah2,ah3, al0,al1,al2,al3;
                ldsm4(ah0, ah1, ah2, ah3, aaddr);
                ldsm4(al0, al1, al2, al3, aaddr + A_PB);
                int bc = kf*2 + bcsel;
#pragma unroll
                for (int bq = 0; bq < 4; bq++) {
                    int bro = bq*16 + brsel;
                    unsigned baddr = bHi + (unsigned)(bro*128 + ((bc ^ (bro&7))*16));
                    uint32_t bh0,bh1,bh2,bh3, bl0,bl1,bl2,bl3;
                    ldsm4(bh0, bh1, bh2, bh3, baddr);
                    ldsm4(bl0, bl1, bl2, bl3, baddr + B_PB);
                    mma16816(acc[2*bq],   ah0,ah1,ah2,ah3, bh0,bh1);
                    mma16816(acc[2*bq],   ah0,ah1,ah2,ah3, bl0,bl1);
                    mma16816(acc[2*bq],   al0,al1,al2,al3, bh0,bh1);
                    mma16816(acc[2*bq+1], ah0,ah1,ah2,ah3, bh2,bh3);
                    mma16816(acc[2*bq+1], ah0,ah1,ah2,ah3, bl2,bl3);
                    mma16816(acc[2*bq+1], al0,al1,al2,al3, bh2,bh3);
                }
            }
        }
    }

    {
        int p0 = mbase + (lane >> 2);
        int p1 = p0 + 8;
        int wA = w0 + p0, wBp = w0 + p1;
        bool v0 = wA < W1, v1 = wBp < W1;
        float* orow = g_y2 + ((size_t)(b*CH)*H1 + h)*W1;
#pragma unroll
        for (int nt = 0; nt < 8; nt++) {
            int co = nt*8 + 2*(lane & 3);
            float bb0 = __ldg(b2 + co), bb1 = __ldg(b2 + co + 1);
            if (v0) {
                orow[(size_t)co*HWp + wA]     = fmaxf(acc[nt][0] + bb0, 0.f);
                orow[(size_t)(co+1)*HWp + wA] = fmaxf(acc[nt][1] + bb1, 0.f);
            }
            if (v1) {
                orow[(size_t)co*HWp + wBp]     = fmaxf(acc[nt][2] + bb0, 0.f);
                orow[(size_t)(co+1)*HWp + wBp] = fmaxf(acc[nt][3] + bb1, 0.f);
            }
        }
    }
}

// ---------------- conv3: 1x1, 128->64 ch, 32-cout groups ----------
__global__ void __launch_bounds__(256)
conv3_k(const float* __restrict__ w3, const float* __restrict__ b3) {
    __shared__ float ws[32*128];
    int t = threadIdx.x;
    int co0 = blockIdx.y * 32;
    for (int j = t; j < 4096; j += 256)
        ws[j] = w3[(co0 + (j >> 7))*128 + (j & 127)];
    __syncthreads();
    int p0 = blockIdx.x*1024 + t*4;
    if (p0 >= Bsz*HWp) return;
    int b = p0 / HWp, hw = p0 - b*HWp;
    const float* ih = g_h1 + (size_t)b*CHWp + hw;
    const float* iy = g_y2 + (size_t)b*CHWp + hw;
    float4 acc[32];
#pragma unroll
    for (int k = 0; k < 32; k++) {
        float bb = b3[co0+k];
        acc[k] = make_float4(bb, bb, bb, bb);
    }
#pragma unroll 2
    for (int ci = 0; ci < 64; ci++) {
        float4 xh = *(const float4*)(ih + (size_t)ci*HWp);
        float4 xy = *(const float4*)(iy + (size_t)ci*HWp);
#pragma unroll
        for (int k = 0; k < 32; k++) {
            float wh = ws[k*128 + ci], wy = ws[k*128 + 64 + ci];
            acc[k].x = fmaf(xh.x, wh, acc[k].x);
            acc[k].y = fmaf(xh.y, wh, acc[k].y);
            acc[k].z = fmaf(xh.z, wh, acc[k].z);
            acc[k].w = fmaf(xh.w, wh, acc[k].w);
            acc[k].x = fmaf(xy.x, wy, acc[k].x);
            acc[k].y = fmaf(xy.y, wy, acc[k].y);
            acc[k].z = fmaf(xy.z, wy, acc[k].z);
            acc[k].w = fmaf(xy.w, wy, acc[k].w);
        }
    }
#pragma unroll
    for (int k = 0; k < 32; k++)
        *(float4*)(g_h3 + (size_t)b*CHWp + (size_t)(co0+k)*HWp + hw) = acc[k];
}

// ---------------- primary capsules ----------
__global__ void pc_k(const float* __restrict__ pw, const float* __restrict__ pb) {
    int n = blockIdx.x*256 + threadIdx.x;
    int b = blockIdx.y;
    if (n >= Ncap) return;
    const float4* uin = (const float4*)(g_h3 + (size_t)b*CHWp + (size_t)n*8);
    float4 q0 = uin[0], q1 = uin[1];
    float ui[8] = {q0.x,q0.y,q0.z,q0.w, q1.x,q1.y,q1.z,q1.w};
    const float4* pbv = (const float4*)(pb + (size_t)n*8);
    float4 r0 = pbv[0], r1 = pbv[1];
    float a[8] = {r0.x,r0.y,r0.z,r0.w, r1.x,r1.y,r1.z,r1.w};
    const float4* pwv = (const float4*)(pw + (size_t)n*64);
#pragma unroll
    for (int i = 0; i < 8; i++) {
        float4 wA = pwv[2*i], wB = pwv[2*i+1];
        a[0] = fmaf(ui[i], wA.x, a[0]); a[1] = fmaf(ui[i], wA.y, a[1]);
        a[2] = fmaf(ui[i], wA.z, a[2]); a[3] = fmaf(ui[i], wA.w, a[3]);
        a[4] = fmaf(ui[i], wB.x, a[4]); a[5] = fmaf(ui[i], wB.y, a[5]);
        a[6] = fmaf(ui[i], wB.z, a[6]); a[7] = fmaf(ui[i], wB.w, a[7]);
    }
    float4* uo = (float4*)(g_u + ((size_t)b*Ncap + n)*8);
    uo[0] = make_float4(a[0],a[1],a[2],a[3]);
    uo[1] = make_float4(a[4],a[5],a[6],a[7]);
}

// ---------------- routing pass: cp.async pipelined, 2-wide ILP -----
#define RGROUP 6
#define RCHUNK 66
#define ECROW 132
#define ECN (Ecls*ECROW)
#define R_SMEM_BYTES ((2*RGROUP*ECN + 2*RGROUP*128) * 4)

__device__ __forceinline__ void cpa16(unsigned d, const void* s) {
    asm volatile("cp.async.cg.shared.global [%0], [%1], 16;" :: "r"(d), "l"(s));
}
__device__ __forceinline__ float shx(float v, int m) {
    return __shfl_xor_sync(0xffffffffu, v, m);
}

__global__ void __launch_bounds__(128)
route_k(const float* __restrict__ ec, int pass) {
    extern __shared__ float rs[];
    float* ecs = rs;
    float* us  = rs + 2*RGROUP*ECN;
    int t = threadIdx.x;
    int b = t >> 3, e = t & 7;
    float* sout = g_s + pass*2048;

    float vs[16];
    const float4* vp = (const float4*)(g_vsum + t*16);
#pragma unroll
    for (int q = 0; q < 4; q++) {
        float4 v = vp[q];
        vs[q*4+0] = v.x; vs[q*4+1] = v.y; vs[q*4+2] = v.z; vs[q*4+3] = v.w;
    }
    float accs[16];
#pragma unroll
    for (int o = 0; o < 16; o++) accs[o] = 0.f;

    int n0 = blockIdx.x * RCHUNK;
    int nEnd = n0 + RCHUNK; if (nEnd > Ncap) nEnd = Ncap;
    int gTot = (nEnd - n0 + RGROUP - 1) / RGROUP;

    auto stage = [&](int g, int buf) {
        int nb = n0 + g*RGROUP;
        unsigned ecd = (unsigned)__cvta_generic_to_shared(ecs + buf*RGROUP*ECN);
        unsigned usd = (unsigned)__cvta_generic_to_shared(us  + buf*RGROUP*128);
#pragma unroll
        for (int j = 0; j < 12; j++) {
            int idx = t + j*128;
            int nl = idx >> 8, c = idx & 255;
            int n = nb + nl;
            if (n < nEnd)
                cpa16(ecd + (unsigned)(nl*ECN + (c>>5)*ECROW + (c&31)*4)*4u,
                      ec + (size_t)n*1024 + c*4);
        }
#pragma unroll
        for (int j = 0; j < 2; j++) {
            int idx = t + j*128;
            if (idx < RGROUP*32) {
                int nl = idx >> 5, lane = idx & 31;
                int n = nb + nl;
                int bb = lane >> 1, half = lane & 1;
                if (n < nEnd)
                    cpa16(usd + (unsigned)(nl*128 + bb*8 + half*4)*4u,
                          g_u + ((size_t)bb*Ncap + n)*8 + half*4);
            }
        }
        asm volatile("cp.async.commit_group;");
    };

    stage(0, 0);
    for (int g = 0; g < gTot; g++) {
        if (g + 1 < gTot) {
            stage(g+1, (g+1)&1);
            asm volatile("cp.async.wait_group 1;");
        } else {
            asm volatile("cp.async.wait_group 0;");
        }
        __syncthreads();
        int cnt = nEnd - (n0 + g*RGROUP);
        if (cnt > RGROUP) cnt = RGROUP;
        const float* eb = ecs + (g&1)*RGROUP*ECN;
        const float* ub = us  + (g&1)*RGROUP*128;
        int nl = 0;
        for (; nl + 1 < cnt; nl += 2) {
            const float* un0 = ub + nl*128 + b*8;
            float4 x0 = *(const float4*)un0;
            float4 x1 = *(const float4*)(un0 + 4);
            float4 y0 = *(const float4*)(un0 + 128);
            float4 y1 = *(const float4*)(un0 + 132);
            float ua[8] = {x0.x,x0.y,x0.z,x0.w, x1.x,x1.y,x1.z,x1.w};
            float ubv[8] = {y0.x,y0.y,y0.z,y0.w, y1.x,y1.y,y1.z,y1.w};
            const float4* ep0 = (const float4*)(eb + nl*ECN + e*ECROW);
            const float4* ep1 = (const float4*)(eb + (nl+1)*ECN + e*ECROW);
            float uh0[16], uh1[16];
            float bl0 = 0.f, bl1 = 0.f;
#pragma unroll
            for (int o = 0; o < 16; o++) {
                float4 wA = ep0[2*o], wB = ep0[2*o+1];
                float s = wA.x*ua[0] + wA.y*ua[1] + wA.z*ua[2] + wA.w*ua[3]
                        + wB.x*ua[4] + wB.y*ua[5] + wB.z*ua[6] + wB.w*ua[7];
                uh0[o] = s; bl0 = fmaf(s, vs[o], bl0);
                float4 wC = ep1[2*o], wD = ep1[2*o+1];
                float s1 = wC.x*ubv[0] + wC.y*ubv[1] + wC.z*ubv[2] + wC.w*ubv[3]
                         + wD.x*ubv[4] + wD.y*ubv[5] + wD.z*ubv[6] + wD.w*ubv[7];
                uh1[o] = s1; bl1 = fmaf(s1, vs[o], bl1);
            }
            float m0 = bl0, m1 = bl1;
            m0 = fmaxf(m0, shx(m0, 1)); m1 = fmaxf(m1, shx(m1, 1));
            m0 = fmaxf(m0, shx(m0, 2)); m1 = fmaxf(m1, shx(m1, 2));
            m0 = fmaxf(m0, shx(m0, 4)); m1 = fmaxf(m1, shx(m1, 4));
            float e0 = __expf(bl0 - m0), e1 = __expf(bl1 - m1);
            float d0 = e0, d1 = e1;
            d0 += shx(d0, 1); d1 += shx(d1, 1);
            d0 += shx(d0, 2); d1 += shx(d1, 2);
            d0 += shx(d0, 4); d1 += shx(d1, 4);
            float c0 = e0 / d0, c1 = e1 / d1;
#pragma unroll
            for (int o = 0; o < 16; o++)
                accs[o] = fmaf(c1, uh1[o], fmaf(c0, uh0[o], accs[o]));
        }
        if (nl < cnt) {
            const float* un = ub + nl*128 + b*8;
            float4 u0 = *(const float4*)un;
            float4 u1 = *(const float4*)(un + 4);
            float ua[8] = {u0.x,u0.y,u0.z,u0.w, u1.x,u1.y,u1.z,u1.w};
            const float4* ep = (const float4*)(eb + nl*ECN + e*ECROW);
            float uh[16];
            float bl = 0.f;
#pragma unroll
            for (int o = 0; o < 16; o++) {
                float4 wA = ep[2*o], wB = ep[2*o+1];
                float s = wA.x*ua[0] + wA.y*ua[1] + wA.z*ua[2] + wA.w*ua[3]
                        + wB.x*ua[4] + wB.y*ua[5] + wB.z*ua[6] + wB.w*ua[7];
                uh[o] = s;
                bl = fmaf(s, vs[o], bl);
            }
            float m = bl;
            m = fmaxf(m, shx(m, 1));
            m = fmaxf(m, shx(m, 2));
            m = fmaxf(m, shx(m, 4));
            float ex = __expf(bl - m);
            float den = ex;
            den += shx(den, 1);
            den += shx(den, 2);
            den += shx(den, 4);
            float c = ex / den;
#pragma unroll
            for (int o = 0; o < 16; o++) accs[o] = fmaf(c, uh[o], accs[o]);
        }
        __syncthreads();
    }
#pragma unroll
    for (int o = 0; o < 16; o++) atomicAdd(sout + t*16 + o, accs[o]);
}

// ---------------- squash + accumulate vsum ----------------
__global__ void squash_k(int pass) {
    int t = threadIdx.x;
    const float* sp = g_s + pass*2048 + t*16;
    float sv[16]; float nn = 0.f;
#pragma unroll
    for (int o = 0; o < 16; o++) { sv[o] = sp[o]; nn = fmaf(sv[o], sv[o], nn); }
    float nrm = sqrtf(nn);
    float sc = nn / (1.f + nn) / (nrm + 1e-8f);
#pragma unroll
    for (int o = 0; o < 16; o++) g_vsum[t*16 + o] += sc * sv[o];
}

__global__ void final_k(float* __restrict__ out) {
    int t = threadIdx.x;
    const float* sp = g_s + 2*2048 + t*16;
    float nn = 0.f;
#pragma unroll
    for (int o = 0; o < 16; o++) { float v = sp[o]; nn = fmaf(v, v, nn); }
    float nrm = sqrtf(nn);
    float sc = nn / (1.f + nn) / (nrm + 1e-8f);
    out[t] = sc * nrm;
}

// ---------------- launch ----------------
extern "C" void kernel_launch(void* const* d_in, const int* in_sizes, int n_in,
                              void* d_out, int out_size) {
    const float* x  = (const float*)d_in[0];
    const float* w1 = (const float*)d_in[1];
    const float* b1 = (const float*)d_in[2];
    const float* w2 = (const float*)d_in[3];
    const float* b2 = (const float*)d_in[4];
    const float* w3 = (const float*)d_in[5];
    const float* b3 = (const float*)d_in[6];
    const float* pw = (const float*)d_in[7];
    const float* pb = (const float*)d_in[8];
    const float* ec = (const float*)d_in[9];
    float* out = (float*)d_out;

    cudaFuncSetAttribute(conv2_mma, cudaFuncAttributeMaxDynamicSharedMemorySize,
                         C2_SMEM);
    cudaFuncSetAttribute(route_k, cudaFuncAttributeMaxDynamicSharedMemorySize,
                         R_SMEM_BYTES);

    zero_k<<<24, 256>>>();
    zerop_k<<<(16*1460*8 + 255)/256, 256>>>();
    splitw2_k<<<(64*2304 + 255)/256, 256>>>(w2);
    conv1_k<<<dim3(7, Bsz), 512>>>(x, w1, b1);
    conv2_mma<<<dim3(2, H1, Bsz), 256, C2_SMEM>>>(b2);
    conv3_k<<<dim3(56, 2), 256>>>(w3, b3);
    pc_k<<<dim3((Ncap + 255)/256, Bsz), 256>>>(pw, pb);

    int rblocks = (Ncap + RCHUNK - 1) / RCHUNK;
    route_k<<<rblocks, 128, R_SMEM_BYTES>>>(ec, 0);
    squash_k<<<1, 128>>>(0);
    route_k<<<rblocks, 128, R_SMEM_BYTES>>>(ec, 1);
    squash_k<<<1, 128>>>(1);
    route_k<<<rblocks, 128, R_SMEM_BYTES>>>(ec, 2);
    final_k<<<1, 128>>>(out);
}

// round 15
// speedup vs baseline: 1.1221x; 1.1221x over previous
#include <cuda_runtime.h>
#include <cuda_bf16.h>
#include <math.h>
#include <stdint.h>

// Shapes
#define Bsz 16
#define CH 64
#define H1 14
#define W1 254
#define HWp (H1*W1)            // 3556
#define CHWp (CH*HWp)          // 227584
#define Ncap 28448
#define Ecls 8
#define ODv 16

// padded NHWC planes for conv2 A operand: rows -2..16 (19), cols -2..261 (264)
#define PRows 19
#define PCols 264
#define PLANE_E ((size_t)Bsz*PRows*PCols*64)

// ---------------- scratch ----------------
__device__ float g_h1[Bsz*CHWp];
__device__ float g_y2[Bsz*CHWp];
__device__ float g_h3[Bsz*CHWp];
__device__ float g_u [Bsz*Ncap*8];
__device__ float g_s [3*2048];
__device__ float g_vsum[2048];
__device__ __nv_bfloat16 g_h1h[PLANE_E];
__device__ __nv_bfloat16 g_h1l[PLANE_E];
__device__ __nv_bfloat16 g_w2t[36*2*4096];   // [tap][hl][co][ci]

__global__ void zero_k() {
    int t = blockIdx.x*256 + threadIdx.x;
    if (t < 3*2048) g_s[t] = 0.f;
    if (t < 2048)   g_vsum[t] = 0.f;
}
// zero only the padding border of the NHWC planes (conv1 fills the interior)
__global__ void zerop_k() {
    int i = blockIdx.x*256 + threadIdx.x;   // 16 b x 1460 pos x 8 chunks
    if (i >= 16*1460*8) return;
    int c8 = i & 7; int r = i >> 3;
    int b = r / 1460; int p = r - b*1460;
    int row, col;
    if (p < 1320) { int rr = p/264; col = p - rr*264; row = rr < 2 ? rr : rr + 14; }
    else { int q = p - 1320; int rr = q/10; int cc = q - rr*10;
           row = 2 + rr; col = cc < 2 ? cc : cc + 254; }
    size_t off = (((size_t)b*PRows + row)*PCols + col)*64 + c8*8;
    uint4 z = make_uint4(0,0,0,0);
    *(uint4*)(g_h1h + off) = z;
    *(uint4*)(g_h1l + off) = z;
}

// ---------------- prep: transpose+split w2 -> [tap][hl][co][ci] bf16 ----
__global__ void splitw2_k(const float* __restrict__ w2) {
    int i = blockIdx.x*256 + threadIdx.x;
    if (i < 64*2304) {
        int co = i / 2304, r = i - co*2304;
        int ci = r / 36, tap = r - ci*36;
        float v = w2[i];
        __nv_bfloat16 h = __float2bfloat16(v);
        __nv_bfloat16 l = __float2bfloat16(v - __bfloat162float(h));
        g_w2t[(tap*2+0)*4096 + co*64 + ci] = h;
        g_w2t[(tap*2+1)*4096 + co*64 + ci] = l;
    }
}

// ---- conv1: 1->64ch 6x6 s2, relu; fp32 + NHWC bf16 hi/lo via smem transpose --
#define C1_SMEM ((4096+2304+64)*4 + 512*17*4)
__global__ void __launch_bounds__(512)
conv1_k(const float* __restrict__ x,
        const float* __restrict__ w1,
        const float* __restrict__ b1) {
    extern __shared__ float c1s[];
    float* xs = c1s;
    float* ws = xs + 4096;
    float* bs = ws + 2304;
    uint32_t* buf = (uint32_t*)(bs + 64);
    int h2 = blockIdx.x, b = blockIdx.y, t = threadIdx.x;
    const float* xrow = x + b*(32*512) + (4*h2)*512;   // rows 4h2..4h2+7
    for (int j = t; j < 4096; j += 512) xs[j] = xrow[j];
    for (int j = t; j < 2304; j += 512) ws[j] = w1[j];
    if (t < 64) bs[t] = b1[t];
    __syncthreads();
    int sub = t >> 8, tw = t & 255;
    bool val = tw < W1;
    int twc = val ? tw : 0;
    float win[36];
#pragma unroll
    for (int r = 0; r < 6; r++)
#pragma unroll
        for (int k = 0; k < 6; k++) win[r*6+k] = xs[(sub*2 + r)*512 + 2*twc + k];
    float* outp = g_h1 + (size_t)(b*CH*H1 + h2*2 + sub)*W1 + twc;
    for (int g = 0; g < 4; g++) {
#pragma unroll
        for (int fp = 0; fp < 8; fp++) {
            int f = g*16 + fp*2;
            float a0 = bs[f], a1 = bs[f+1];
            const float* wp0 = ws + f*36;
            const float* wp1 = wp0 + 36;
#pragma unroll
            for (int k = 0; k < 36; k++) {
                a0 = fmaf(win[k], wp0[k], a0);
                a1 = fmaf(win[k], wp1[k], a1);
            }
            a0 = fmaxf(a0, 0.f); a1 = fmaxf(a1, 0.f);
            if (val) {
                outp[(size_t)f*HWp]     = a0;
                outp[(size_t)(f+1)*HWp] = a1;
            }
            __nv_bfloat162 hv = __floats2bfloat162_rn(a0, a1);
            __nv_bfloat162 lv = __floats2bfloat162_rn(
                a0 - __bfloat162float(hv.x), a1 - __bfloat162float(hv.y));
            buf[t*17 + fp]     = *(uint32_t*)&hv;
            buf[t*17 + 8 + fp] = *(uint32_t*)&lv;
        }
        __syncthreads();
#pragma unroll
        for (int i = 0; i < 4; i++) {
            int j = t + i*512;
            int pos = j >> 2, q = j & 3;
            int psub = pos >> 8, ptw = pos & 255;
            if (ptw < W1) {
                const uint32_t* src = buf + pos*17 + (q >> 1)*8 + (q & 1)*4;
                uint4 v = make_uint4(src[0], src[1], src[2], src[3]);
                size_t boff = ((((size_t)b*PRows + h2*2 + psub + 2)*PCols + ptw + 2)*64
                               + g*16)*2 + (q & 1)*16;
                char* base = (char*)((q < 2) ? g_h1h : g_h1l);
                *(uint4*)(base + boff) = v;
            }
        }
        __syncthreads();
    }
}

// ===== conv2: tap-decomposed GEMM, pure-cp.async staging, ldmatrix ======
#define AROWS 134
#define A_PB (AROWS*128)
#define B_PB (64*128)
#define C2S_A (4*A_PB)
#define C2S_B (4*B_PB)
#define C2_SMEM (C2S_A + C2S_B)

static __device__ __forceinline__ void mma16816(float* c,
    uint32_t a0, uint32_t a1, uint32_t a2, uint32_t a3,
    uint32_t b0, uint32_t b1) {
    asm volatile(
        "mma.sync.aligned.m16n8k16.row.col.f32.bf16.bf16.f32 "
        "{%0,%1,%2,%3}, {%4,%5,%6,%7}, {%8,%9}, {%0,%1,%2,%3};"
        : "+f"(c[0]), "+f"(c[1]), "+f"(c[2]), "+f"(c[3])
        : "r"(a0), "r"(a1), "r"(a2), "r"(a3), "r"(b0), "r"(b1));
}
static __device__ __forceinline__ void ldsm4(uint32_t& r0, uint32_t& r1,
    uint32_t& r2, uint32_t& r3, unsigned a) {
    asm volatile("ldmatrix.sync.aligned.m8n8.x4.shared.b16 {%0,%1,%2,%3}, [%4];"
        : "=r"(r0), "=r"(r1), "=r"(r2), "=r"(r3) : "r"(a));
}
__device__ __forceinline__ void cpa16g(unsigned d, const void* s) {
    asm volatile("cp.async.cg.shared.global [%0], [%1], 16;" :: "r"(d), "l"(s));
}

__global__ void __launch_bounds__(256, 2)
conv2_mma(const float* __restrict__ b2) {
    extern __shared__ char cs2[];
    unsigned sA, sB;
    { unsigned u; asm("{ .reg .u64 tp; cvta.to.shared.u64 tp, %1; cvt.u32.u64 %0, tp; }"
                      : "=r"(u) : "l"(cs2));
      sA = u; sB = u + C2S_A; }

    const int wt = blockIdx.x, h = blockIdx.y, b = blockIdx.z;
    const int t = threadIdx.x, lane = t & 31, wid = t >> 5;
    const int mbase = wid * 16;
    const int w0 = wt * 128;

    float acc[8][4];
#pragma unroll
    for (int nt = 0; nt < 8; nt++)
#pragma unroll
        for (int q = 0; q < 4; q++) acc[nt][q] = 0.f;

    auto stageA = [&](int kh, int buf) {
        const char* ph = (const char*)(g_h1h + (((size_t)b*PRows + h+kh)*PCols + w0)*64);
        const char* pl = (const char*)(g_h1l + (((size_t)b*PRows + h+kh)*PCols + w0)*64);
#pragma unroll
        for (int i = 0; i < 9; i++) {
            int idx = t + i*256;
            if (idx < 2144) {
                int hl = idx >= 1072;
                int r = idx - hl*1072;
                int pp = r >> 3, c = r & 7;
                cpa16g(sA + (unsigned)((buf*2+hl)*A_PB + pp*128 + ((c^(pp&7))*16)),
                       (hl ? pl : ph) + pp*128 + c*16);
            }
        }
        asm volatile("cp.async.commit_group;");
    };
    auto stageB = [&](int tap, int buf) {
#pragma unroll
        for (int i = 0; i < 4; i++) {
            int idx = t + i*256;
            int hl = idx >> 9;
            int r = idx & 511;
            int co = r >> 3, c = r & 7;
            cpa16g(sB + (unsigned)((buf*2+hl)*B_PB + co*128 + ((c^(co&7))*16)),
                   (const char*)(g_w2t + (size_t)(tap*2+hl)*4096 + co*64) + c*16);
        }
        asm volatile("cp.async.commit_group;");
    };

    stageA(0, 0);
    stageB(0, 0);
    stageB(1, 1);
    asm volatile("cp.async.wait_group 1;");
    __syncthreads();

    const int arsel = (lane & 7) + ((lane >> 3) & 1)*8;
    const int acsel = (lane >> 4) & 1;
    const int brsel = (lane & 7) + ((lane >> 4) & 1)*8;
    const int bcsel = (lane >> 3) & 1;

    for (int kh = 0; kh < 6; kh++) {
        const unsigned aHi = sA + (unsigned)(kh & 1)*2*A_PB;
#pragma unroll 1
        for (int kw = 0; kw < 6; kw++) {
            const int tap = kh*6 + kw;
            if (tap > 0) __syncthreads();
            if (tap >= 1 && tap + 1 <= 35) stageB(tap + 1, (tap + 1) & 1);
            if (kw == 4 && kh < 5) stageA(kh + 1, (kh + 1) & 1);
            asm volatile("cp.async.wait_group 1;");
            __syncthreads();

            const unsigned bHi = sB + (unsigned)(tap & 1)*2*B_PB;
            const int arow = mbase + kw + arsel;
            const unsigned aBase = aHi + (unsigned)(arow*128);
            const int axr = (arow & 7);
#pragma unroll
            for (int kf = 0; kf < 4; kf++) {
                int ac = kf*2 + acsel;
                unsigned aaddr = aBase + (unsigned)(((ac ^ axr))*16);
                uint32_t ah0,ah1,ah2,ah3, al0,al1,al2,al3;
                ldsm4(ah0, ah1, ah2, ah3, aaddr);
                ldsm4(al0, al1, al2, al3, aaddr + A_PB);
                int bc = kf*2 + bcsel;
#pragma unroll
                for (int bq = 0; bq < 4; bq++) {
                    int bro = bq*16 + brsel;
                    unsigned baddr = bHi + (unsigned)(bro*128 + ((bc ^ (bro&7))*16));
                    uint32_t bh0,bh1,bh2,bh3, bl0,bl1,bl2,bl3;
                    ldsm4(bh0, bh1, bh2, bh3, baddr);
                    ldsm4(bl0, bl1, bl2, bl3, baddr + B_PB);
                    mma16816(acc[2*bq],   ah0,ah1,ah2,ah3, bh0,bh1);
                    mma16816(acc[2*bq],   ah0,ah1,ah2,ah3, bl0,bl1);
                    mma16816(acc[2*bq],   al0,al1,al2,al3, bh0,bh1);
                    mma16816(acc[2*bq+1], ah0,ah1,ah2,ah3, bh2,bh3);
                    mma16816(acc[2*bq+1], ah0,ah1,ah2,ah3, bl2,bl3);
                    mma16816(acc[2*bq+1], al0,al1,al2,al3, bh2,bh3);
                }
            }
        }
    }

    {
        int p0 = mbase + (lane >> 2);
        int p1 = p0 + 8;
        int wA = w0 + p0, wBp = w0 + p1;
        bool v0 = wA < W1, v1 = wBp < W1;
        float* orow = g_y2 + ((size_t)(b*CH)*H1 + h)*W1;
#pragma unroll
        for (int nt = 0; nt < 8; nt++) {
            int co = nt*8 + 2*(lane & 3);
            float bb0 = __ldg(b2 + co), bb1 = __ldg(b2 + co + 1);
            if (v0) {
                orow[(size_t)co*HWp + wA]     = fmaxf(acc[nt][0] + bb0, 0.f);
                orow[(size_t)(co+1)*HWp + wA] = fmaxf(acc[nt][1] + bb1, 0.f);
            }
            if (v1) {
                orow[(size_t)co*HWp + wBp]     = fmaxf(acc[nt][2] + bb0, 0.f);
                orow[(size_t)(co+1)*HWp + wBp] = fmaxf(acc[nt][3] + bb1, 0.f);
            }
        }
    }
}

// ---------------- conv3: 1x1, 128->64 ch, 32-cout groups ----------
__global__ void __launch_bounds__(256)
conv3_k(const float* __restrict__ w3, const float* __restrict__ b3) {
    __shared__ float ws[32*128];
    int t = threadIdx.x;
    int co0 = blockIdx.y * 32;
    for (int j = t; j < 4096; j += 256)
        ws[j] = w3[(co0 + (j >> 7))*128 + (j & 127)];
    __syncthreads();
    int p0 = blockIdx.x*1024 + t*4;
    if (p0 >= Bsz*HWp) return;
    int b = p0 / HWp, hw = p0 - b*HWp;
    const float* ih = g_h1 + (size_t)b*CHWp + hw;
    const float* iy = g_y2 + (size_t)b*CHWp + hw;
    float4 acc[32];
#pragma unroll
    for (int k = 0; k < 32; k++) {
        float bb = b3[co0+k];
        acc[k] = make_float4(bb, bb, bb, bb);
    }
#pragma unroll 2
    for (int ci = 0; ci < 64; ci++) {
        float4 xh = *(const float4*)(ih + (size_t)ci*HWp);
        float4 xy = *(const float4*)(iy + (size_t)ci*HWp);
#pragma unroll
        for (int k = 0; k < 32; k++) {
            float wh = ws[k*128 + ci], wy = ws[k*128 + 64 + ci];
            acc[k].x = fmaf(xh.x, wh, acc[k].x);
            acc[k].y = fmaf(xh.y, wh, acc[k].y);
            acc[k].z = fmaf(xh.z, wh, acc[k].z);
            acc[k].w = fmaf(xh.w, wh, acc[k].w);
            acc[k].x = fmaf(xy.x, wy, acc[k].x);
            acc[k].y = fmaf(xy.y, wy, acc[k].y);
            acc[k].z = fmaf(xy.z, wy, acc[k].z);
            acc[k].w = fmaf(xy.w, wy, acc[k].w);
        }
    }
#pragma unroll
    for (int k = 0; k < 32; k++)
        *(float4*)(g_h3 + (size_t)b*CHWp + (size_t)(co0+k)*HWp + hw) = acc[k];
}

// ---------------- primary capsules ----------
__global__ void pc_k(const float* __restrict__ pw, const float* __restrict__ pb) {
    int n = blockIdx.x*256 + threadIdx.x;
    int b = blockIdx.y;
    if (n >= Ncap) return;
    const float4* uin = (const float4*)(g_h3 + (size_t)b*CHWp + (size_t)n*8);
    float4 q0 = uin[0], q1 = uin[1];
    float ui[8] = {q0.x,q0.y,q0.z,q0.w, q1.x,q1.y,q1.z,q1.w};
    const float4* pbv = (const float4*)(pb + (size_t)n*8);
    float4 r0 = pbv[0], r1 = pbv[1];
    float a[8] = {r0.x,r0.y,r0.z,r0.w, r1.x,r1.y,r1.z,r1.w};
    const float4* pwv = (const float4*)(pw + (size_t)n*64);
#pragma unroll
    for (int i = 0; i < 8; i++) {
        float4 wA = pwv[2*i], wB = pwv[2*i+1];
        a[0] = fmaf(ui[i], wA.x, a[0]); a[1] = fmaf(ui[i], wA.y, a[1]);
        a[2] = fmaf(ui[i], wA.z, a[2]); a[3] = fmaf(ui[i], wA.w, a[3]);
        a[4] = fmaf(ui[i], wB.x, a[4]); a[5] = fmaf(ui[i], wB.y, a[5]);
        a[6] = fmaf(ui[i], wB.z, a[6]); a[7] = fmaf(ui[i], wB.w, a[7]);
    }
    float4* uo = (float4*)(g_u + ((size_t)b*Ncap + n)*8);
    uo[0] = make_float4(a[0],a[1],a[2],a[3]);
    uo[1] = make_float4(a[4],a[5],a[6],a[7]);
}

// ---- pass 0 as GEMM: s = 0.125 * sum_n u_hat (c is exactly 1/8) ----
// thread t owns (e,o) = (t>>4, t&15); 16 b-accumulators; ec streamed once.
#define S0CH 66
__global__ void __launch_bounds__(128)
s0_k(const float* __restrict__ ec) {
    __shared__ float us[S0CH*128];
    int t = threadIdx.x;
    int n0 = blockIdx.x * S0CH;
    int nEnd = n0 + S0CH; if (nEnd > Ncap) nEnd = Ncap;
    int cnt = nEnd - n0;
    for (int j = t; j < cnt*32; j += 128) {
        int nl = j >> 5, lane = j & 31;
        int bb = lane >> 1, half = lane & 1;
        *(float4*)(us + nl*128 + bb*8 + half*4) =
            *(const float4*)(g_u + ((size_t)bb*Ncap + n0 + nl)*8 + half*4);
    }
    __syncthreads();
    float acc[16];
#pragma unroll
    for (int bb = 0; bb < 16; bb++) acc[bb] = 0.f;
    const float* ep = ec + (size_t)n0*1024 + t*8;
    float4 w0 = *(const float4*)ep;
    float4 w1 = *(const float4*)(ep + 4);
    for (int nl = 0; nl < cnt; nl++) {
        float4 c0 = w0, c1 = w1;
        if (nl + 1 < cnt) {
            w0 = *(const float4*)(ep + (size_t)(nl+1)*1024);
            w1 = *(const float4*)(ep + (size_t)(nl+1)*1024 + 4);
        }
        const float* ub = us + nl*128;
#pragma unroll
        for (int bb = 0; bb < 16; bb++) {
            float4 u0 = *(const float4*)(ub + bb*8);
            float4 u1 = *(const float4*)(ub + bb*8 + 4);
            float s = c0.x*u0.x + c0.y*u0.y + c0.z*u0.z + c0.w*u0.w
                    + c1.x*u1.x + c1.y*u1.y + c1.z*u1.z + c1.w*u1.w;
            acc[bb] += s;
        }
    }
#pragma unroll
    for (int bb = 0; bb < 16; bb++)
        atomicAdd(g_s + bb*128 + t, 0.125f * acc[bb]);
}

// ---------------- routing pass (1,2): cp.async pipelined, 2-wide ILP -----
#define RGROUP 6
#define RCHUNK 66
#define ECROW 132
#define ECN (Ecls*ECROW)
#define R_SMEM_BYTES ((2*RGROUP*ECN + 2*RGROUP*128) * 4)

__device__ __forceinline__ void cpa16(unsigned d, const void* s) {
    asm volatile("cp.async.cg.shared.global [%0], [%1], 16;" :: "r"(d), "l"(s));
}
__device__ __forceinline__ float shx(float v, int m) {
    return __shfl_xor_sync(0xffffffffu, v, m);
}

__global__ void __launch_bounds__(128)
route_k(const float* __restrict__ ec, int pass) {
    extern __shared__ float rs[];
    float* ecs = rs;
    float* us  = rs + 2*RGROUP*ECN;
    int t = threadIdx.x;
    int b = t >> 3, e = t & 7;
    float* sout = g_s + pass*2048;

    float vs[16];
    const float4* vp = (const float4*)(g_vsum + t*16);
#pragma unroll
    for (int q = 0; q < 4; q++) {
        float4 v = vp[q];
        vs[q*4+0] = v.x; vs[q*4+1] = v.y; vs[q*4+2] = v.z; vs[q*4+3] = v.w;
    }
    float accs[16];
#pragma unroll
    for (int o = 0; o < 16; o++) accs[o] = 0.f;

    int n0 = blockIdx.x * RCHUNK;
    int nEnd = n0 + RCHUNK; if (nEnd > Ncap) nEnd = Ncap;
    int gTot = (nEnd - n0 + RGROUP - 1) / RGROUP;

    auto stage = [&](int g, int buf) {
        int nb = n0 + g*RGROUP;
        unsigned ecd = (unsigned)__cvta_generic_to_shared(ecs + buf*RGROUP*ECN);
        unsigned usd = (unsigned)__cvta_generic_to_shared(us  + buf*RGROUP*128);
#pragma unroll
        for (int j = 0; j < 12; j++) {
            int idx = t + j*128;
            int nl = idx >> 8, c = idx & 255;
            int n = nb + nl;
            if (n < nEnd)
                cpa16(ecd + (unsigned)(nl*ECN + (c>>5)*ECROW + (c&31)*4)*4u,
                      ec + (size_t)n*1024 + c*4);
        }
#pragma unroll
        for (int j = 0; j < 2; j++) {
            int idx = t + j*128;
            if (idx < RGROUP*32) {
                int nl = idx >> 5, lane = idx & 31;
                int n = nb + nl;
                int bb = lane >> 1, half = lane & 1;
                if (n < nEnd)
                    cpa16(usd + (unsigned)(nl*128 + bb*8 + half*4)*4u,
                          g_u + ((size_t)bb*Ncap + n)*8 + half*4);
            }
        }
        asm volatile("cp.async.commit_group;");
    };

    stage(0, 0);
    for (int g = 0; g < gTot; g++) {
        if (g + 1 < gTot) {
            stage(g+1, (g+1)&1);
            asm volatile("cp.async.wait_group 1;");
        } else {
            asm volatile("cp.async.wait_group 0;");
        }
        __syncthreads();
        int cnt = nEnd - (n0 + g*RGROUP);
        if (cnt > RGROUP) cnt = RGROUP;
        const float* eb = ecs + (g&1)*RGROUP*ECN;
        const float* ub = us  + (g&1)*RGROUP*128;
        int nl = 0;
        for (; nl + 1 < cnt; nl += 2) {
            const float* un0 = ub + nl*128 + b*8;
            float4 x0 = *(const float4*)un0;
            float4 x1 = *(const float4*)(un0 + 4);
            float4 y0 = *(const float4*)(un0 + 128);
            float4 y1 = *(const float4*)(un0 + 132);
            float ua[8] = {x0.x,x0.y,x0.z,x0.w, x1.x,x1.y,x1.z,x1.w};
            float ubv[8] = {y0.x,y0.y,y0.z,y0.w, y1.x,y1.y,y1.z,y1.w};
            const float4* ep0 = (const float4*)(eb + nl*ECN + e*ECROW);
            const float4* ep1 = (const float4*)(eb + (nl+1)*ECN + e*ECROW);
            float uh0[16], uh1[16];
            float bl0 = 0.f, bl1 = 0.f;
#pragma unroll
            for (int o = 0; o < 16; o++) {
                float4 wA = ep0[2*o], wB = ep0[2*o+1];
                float s = wA.x*ua[0] + wA.y*ua[1] + wA.z*ua[2] + wA.w*ua[3]
                        + wB.x*ua[4] + wB.y*ua[5] + wB.z*ua[6] + wB.w*ua[7];
                uh0[o] = s; bl0 = fmaf(s, vs[o], bl0);
                float4 wC = ep1[2*o], wD = ep1[2*o+1];
                float s1 = wC.x*ubv[0] + wC.y*ubv[1] + wC.z*ubv[2] + wC.w*ubv[3]
                         + wD.x*ubv[4] + wD.y*ubv[5] + wD.z*ubv[6] + wD.w*ubv[7];
                uh1[o] = s1; bl1 = fmaf(s1, vs[o], bl1);
            }
            float m0 = bl0, m1 = bl1;
            m0 = fmaxf(m0, shx(m0, 1)); m1 = fmaxf(m1, shx(m1, 1));
            m0 = fmaxf(m0, shx(m0, 2)); m1 = fmaxf(m1, shx(m1, 2));
            m0 = fmaxf(m0, shx(m0, 4)); m1 = fmaxf(m1, shx(m1, 4));
            float e0 = __expf(bl0 - m0), e1 = __expf(bl1 - m1);
            float d0 = e0, d1 = e1;
            d0 += shx(d0, 1); d1 += shx(d1, 1);
            d0 += shx(d0, 2); d1 += shx(d1, 2);
            d0 += shx(d0, 4); d1 += shx(d1, 4);
            float c0 = e0 / d0, c1 = e1 / d1;
#pragma unroll
            for (int o = 0; o < 16; o++)
                accs[o] = fmaf(c1, uh1[o], fmaf(c0, uh0[o], accs[o]));
        }
        if (nl < cnt) {
            const float* un = ub + nl*128 + b*8;
            float4 u0 = *(const float4*)un;
            float4 u1 = *(const float4*)(un + 4);
            float ua[8] = {u0.x,u0.y,u0.z,u0.w, u1.x,u1.y,u1.z,u1.w};
            const float4* ep = (const float4*)(eb + nl*ECN + e*ECROW);
            float uh[16];
            float bl = 0.f;
#pragma unroll
            for (int o = 0; o < 16; o++) {
                float4 wA = ep[2*o], wB = ep[2*o+1];
                float s = wA.x*ua[0] + wA.y*ua[1] + wA.z*ua[2] + wA.w*ua[3]
                        + wB.x*ua[4] + wB.y*ua[5] + wB.z*ua[6] + wB.w*ua[7];
                uh[o] = s;
                bl = fmaf(s, vs[o], bl);
            }
            float m = bl;
            m = fmaxf(m, shx(m, 1));
            m = fmaxf(m, shx(m, 2));
            m = fmaxf(m, shx(m, 4));
            float ex = __expf(bl - m);
            float den = ex;
            den += shx(den, 1);
            den += shx(den, 2);
            den += shx(den, 4);
            float c = ex / den;
#pragma unroll
            for (int o = 0; o < 16; o++) accs[o] = fmaf(c, uh[o], accs[o]);
        }
        __syncthreads();
    }
#pragma unroll
    for (int o = 0; o < 16; o++) atomicAdd(sout + t*16 + o, accs[o]);
}

// ---------------- squash + accumulate vsum ----------------
__global__ void squash_k(int pass) {
    int t = threadIdx.x;
    const float* sp = g_s + pass*2048 + t*16;
    float sv[16]; float nn = 0.f;
#pragma unroll
    for (int o = 0; o < 16; o++) { sv[o] = sp[o]; nn = fmaf(sv[o], sv[o], nn); }
    float nrm = sqrtf(nn);
    float sc = nn / (1.f + nn) / (nrm + 1e-8f);
#pragma unroll
    for (int o = 0; o < 16; o++) g_vsum[t*16 + o] += sc * sv[o];
}

__global__ void final_k(float* __restrict__ out) {
    int t = threadIdx.x;
    const float* sp = g_s + 2*2048 + t*16;
    float nn = 0.f;
#pragma unroll
    for (int o = 0; o < 16; o++) { float v = sp[o]; nn = fmaf(v, v, nn); }
    float nrm = sqrtf(nn);
    float sc = nn / (1.f + nn) / (nrm + 1e-8f);
    out[t] = sc * nrm;
}

// ---------------- launch ----------------
extern "C" void kernel_launch(void* const* d_in, const int* in_sizes, int n_in,
                              void* d_out, int out_size) {
    const float* x  = (const float*)d_in[0];
    const float* w1 = (const float*)d_in[1];
    const float* b1 = (const float*)d_in[2];
    const float* w2 = (const float*)d_in[3];
    const float* b2 = (const float*)d_in[4];
    const float* w3 = (const float*)d_in[5];
    const float* b3 = (const float*)d_in[6];
    const float* pw = (const float*)d_in[7];
    const float* pb = (const float*)d_in[8];
    const float* ec = (const float*)d_in[9];
    float* out = (float*)d_out;

    cudaFuncSetAttribute(conv1_k, cudaFuncAttributeMaxDynamicSharedMemorySize,
                         C1_SMEM);
    cudaFuncSetAttribute(conv2_mma, cudaFuncAttributeMaxDynamicSharedMemorySize,
                         C2_SMEM);
    cudaFuncSetAttribute(route_k, cudaFuncAttributeMaxDynamicSharedMemorySize,
                         R_SMEM_BYTES);

    zero_k<<<24, 256>>>();
    zerop_k<<<(16*1460*8 + 255)/256, 256>>>();
    splitw2_k<<<(64*2304 + 255)/256, 256>>>(w2);
    conv1_k<<<dim3(7, Bsz), 512, C1_SMEM>>>(x, w1, b1);
    conv2_mma<<<dim3(2, H1, Bsz), 256, C2_SMEM>>>(b2);
    conv3_k<<<dim3(56, 2), 256>>>(w3, b3);
    pc_k<<<dim3((Ncap + 255)/256, Bsz), 256>>>(pw, pb);

    int rblocks = (Ncap + RCHUNK - 1) / RCHUNK;
    s0_k<<<(Ncap + S0CH - 1)/S0CH, 128>>>(ec);
    squash_k<<<1, 128>>>(0);
    route_k<<<rblocks, 128, R_SMEM_BYTES>>>(ec, 1);
    squash_k<<<1, 128>>>(1);
    route_k<<<rblocks, 128, R_SMEM_BYTES>>>(ec, 2);
    final_k<<<1, 128>>>(out);
}

// round 16
// speedup vs baseline: 1.1285x; 1.0057x over previous
#include <cuda_runtime.h>
#include <cuda_bf16.h>
#include <math.h>
#include <stdint.h>

// Shapes
#define Bsz 16
#define CH 64
#define H1 14
#define W1 254
#define HWp (H1*W1)            // 3556
#define CHWp (CH*HWp)          // 227584
#define Ncap 28448
#define Ecls 8
#define ODv 16

// padded NHWC planes for conv2 A operand: rows -2..16 (19), cols -2..261 (264)
#define PRows 19
#define PCols 264
#define PLANE_E ((size_t)Bsz*PRows*PCols*64)

// ---------------- scratch ----------------
__device__ float g_h1[Bsz*CHWp];
__device__ float g_y2[Bsz*CHWp];
__device__ float g_h3[Bsz*CHWp];
__device__ float g_u [Bsz*Ncap*8];
__device__ float g_s [3*2048];
__device__ float g_vsum[2048];
__device__ __nv_bfloat16 g_h1h[PLANE_E];
__device__ __nv_bfloat16 g_h1l[PLANE_E];
__device__ __nv_bfloat16 g_w2t[36*2*4096];   // [tap][hl][co][ci]

__global__ void zero_k() {
    int t = blockIdx.x*256 + threadIdx.x;
    if (t < 3*2048) g_s[t] = 0.f;
    if (t < 2048)   g_vsum[t] = 0.f;
}
// zero only the padding border of the NHWC planes (conv1 fills the interior)
__global__ void zerop_k() {
    int i = blockIdx.x*256 + threadIdx.x;   // 16 b x 1460 pos x 8 chunks
    if (i >= 16*1460*8) return;
    int c8 = i & 7; int r = i >> 3;
    int b = r / 1460; int p = r - b*1460;
    int row, col;
    if (p < 1320) { int rr = p/264; col = p - rr*264; row = rr < 2 ? rr : rr + 14; }
    else { int q = p - 1320; int rr = q/10; int cc = q - rr*10;
           row = 2 + rr; col = cc < 2 ? cc : cc + 254; }
    size_t off = (((size_t)b*PRows + row)*PCols + col)*64 + c8*8;
    uint4 z = make_uint4(0,0,0,0);
    *(uint4*)(g_h1h + off) = z;
    *(uint4*)(g_h1l + off) = z;
}

// ---------------- prep: transpose+split w2 -> [tap][hl][co][ci] bf16 ----
__global__ void splitw2_k(const float* __restrict__ w2) {
    int i = blockIdx.x*256 + threadIdx.x;
    if (i < 64*2304) {
        int co = i / 2304, r = i - co*2304;
        int ci = r / 36, tap = r - ci*36;
        float v = w2[i];
        __nv_bfloat16 h = __float2bfloat16(v);
        __nv_bfloat16 l = __float2bfloat16(v - __bfloat162float(h));
        g_w2t[(tap*2+0)*4096 + co*64 + ci] = h;
        g_w2t[(tap*2+1)*4096 + co*64 + ci] = l;
    }
}

// ---- conv1: 1->64ch 6x6 s2, relu; fp32 + NHWC bf16 hi/lo via smem transpose --
#define C1_SMEM ((4096+2304+64)*4 + 512*17*4)
__global__ void __launch_bounds__(512)
conv1_k(const float* __restrict__ x,
        const float* __restrict__ w1,
        const float* __restrict__ b1) {
    extern __shared__ float c1s[];
    float* xs = c1s;
    float* ws = xs + 4096;
    float* bs = ws + 2304;
    uint32_t* buf = (uint32_t*)(bs + 64);
    int h2 = blockIdx.x, b = blockIdx.y, t = threadIdx.x;
    const float* xrow = x + b*(32*512) + (4*h2)*512;   // rows 4h2..4h2+7
    for (int j = t; j < 4096; j += 512) xs[j] = xrow[j];
    for (int j = t; j < 2304; j += 512) ws[j] = w1[j];
    if (t < 64) bs[t] = b1[t];
    __syncthreads();
    int sub = t >> 8, tw = t & 255;
    bool val = tw < W1;
    int twc = val ? tw : 0;
    float win[36];
#pragma unroll
    for (int r = 0; r < 6; r++)
#pragma unroll
        for (int k = 0; k < 6; k++) win[r*6+k] = xs[(sub*2 + r)*512 + 2*twc + k];
    float* outp = g_h1 + (size_t)(b*CH*H1 + h2*2 + sub)*W1 + twc;
    for (int g = 0; g < 4; g++) {
#pragma unroll
        for (int fp = 0; fp < 8; fp++) {
            int f = g*16 + fp*2;
            float a0 = bs[f], a1 = bs[f+1];
            const float* wp0 = ws + f*36;
            const float* wp1 = wp0 + 36;
#pragma unroll
            for (int k = 0; k < 36; k++) {
                a0 = fmaf(win[k], wp0[k], a0);
                a1 = fmaf(win[k], wp1[k], a1);
            }
            a0 = fmaxf(a0, 0.f); a1 = fmaxf(a1, 0.f);
            if (val) {
                outp[(size_t)f*HWp]     = a0;
                outp[(size_t)(f+1)*HWp] = a1;
            }
            __nv_bfloat162 hv = __floats2bfloat162_rn(a0, a1);
            __nv_bfloat162 lv = __floats2bfloat162_rn(
                a0 - __bfloat162float(hv.x), a1 - __bfloat162float(hv.y));
            buf[t*17 + fp]     = *(uint32_t*)&hv;
            buf[t*17 + 8 + fp] = *(uint32_t*)&lv;
        }
        __syncthreads();
#pragma unroll
        for (int i = 0; i < 4; i++) {
            int j = t + i*512;
            int pos = j >> 2, q = j & 3;
            int psub = pos >> 8, ptw = pos & 255;
            if (ptw < W1) {
                const uint32_t* src = buf + pos*17 + (q >> 1)*8 + (q & 1)*4;
                uint4 v = make_uint4(src[0], src[1], src[2], src[3]);
                size_t boff = ((((size_t)b*PRows + h2*2 + psub + 2)*PCols + ptw + 2)*64
                               + g*16)*2 + (q & 1)*16;
                char* base = (char*)((q < 2) ? g_h1h : g_h1l);
                *(uint4*)(base + boff) = v;
            }
        }
        __syncthreads();
    }
}

// ===== conv2: tap-decomposed GEMM; single-buffered A, double B; 3 CTA/SM ====
#define AROWS 134
#define A_PB (AROWS*128)             // 17152 bytes per hl A tile
#define B_PB (64*128)                // 8192
#define C2S_A (2*A_PB)               // 34304
#define C2S_B (4*B_PB)               // 32768
#define C2_SMEM (C2S_A + C2S_B)      // 67072

static __device__ __forceinline__ void mma16816(float* c,
    uint32_t a0, uint32_t a1, uint32_t a2, uint32_t a3,
    uint32_t b0, uint32_t b1) {
    asm volatile(
        "mma.sync.aligned.m16n8k16.row.col.f32.bf16.bf16.f32 "
        "{%0,%1,%2,%3}, {%4,%5,%6,%7}, {%8,%9}, {%0,%1,%2,%3};"
        : "+f"(c[0]), "+f"(c[1]), "+f"(c[2]), "+f"(c[3])
        : "r"(a0), "r"(a1), "r"(a2), "r"(a3), "r"(b0), "r"(b1));
}
static __device__ __forceinline__ void ldsm4(uint32_t& r0, uint32_t& r1,
    uint32_t& r2, uint32_t& r3, unsigned a) {
    asm volatile("ldmatrix.sync.aligned.m8n8.x4.shared.b16 {%0,%1,%2,%3}, [%4];"
        : "=r"(r0), "=r"(r1), "=r"(r2), "=r"(r3) : "r"(a));
}
__device__ __forceinline__ void cpa16g(unsigned d, const void* s) {
    asm volatile("cp.async.cg.shared.global [%0], [%1], 16;" :: "r"(d), "l"(s));
}

__global__ void __launch_bounds__(256, 3)
conv2_mma(const float* __restrict__ b2) {
    extern __shared__ char cs2[];
    unsigned sA, sB;
    { unsigned u; asm("{ .reg .u64 tp; cvta.to.shared.u64 tp, %1; cvt.u32.u64 %0, tp; }"
                      : "=r"(u) : "l"(cs2));
      sA = u; sB = u + C2S_A; }

    const int wt = blockIdx.x, h = blockIdx.y, b = blockIdx.z;
    const int t = threadIdx.x, lane = t & 31, wid = t >> 5;
    const int mbase = wid * 16;
    const int w0 = wt * 128;

    float acc[8][4];
#pragma unroll
    for (int nt = 0; nt < 8; nt++)
#pragma unroll
        for (int q = 0; q < 4; q++) acc[nt][q] = 0.f;

    auto stageA = [&](int kh) {
        const char* ph = (const char*)(g_h1h + (((size_t)b*PRows + h+kh)*PCols + w0)*64);
        const char* pl = (const char*)(g_h1l + (((size_t)b*PRows + h+kh)*PCols + w0)*64);
#pragma unroll
        for (int i = 0; i < 9; i++) {
            int idx = t + i*256;
            if (idx < 2144) {
                int hl = idx >= 1072;
                int r = idx - hl*1072;
                int pp = r >> 3, c = r & 7;
                cpa16g(sA + (unsigned)(hl*A_PB + pp*128 + ((c^(pp&7))*16)),
                       (hl ? pl : ph) + pp*128 + c*16);
            }
        }
        asm volatile("cp.async.commit_group;");
    };
    auto stageB = [&](int tap, int buf) {
#pragma unroll
        for (int i = 0; i < 4; i++) {
            int idx = t + i*256;
            int hl = idx >> 9;
            int r = idx & 511;
            int co = r >> 3, c = r & 7;
            cpa16g(sB + (unsigned)((buf*2+hl)*B_PB + co*128 + ((c^(co&7))*16)),
                   (const char*)(g_w2t + (size_t)(tap*2+hl)*4096 + co*64) + c*16);
        }
        asm volatile("cp.async.commit_group;");
    };

    stageB(0, 0);
    stageA(0);
    asm volatile("cp.async.wait_group 0;");
    __syncthreads();

    const int arsel = (lane & 7) + ((lane >> 3) & 1)*8;
    const int acsel = (lane >> 4) & 1;
    const int brsel = (lane & 7) + ((lane >> 4) & 1)*8;
    const int bcsel = (lane >> 3) & 1;

    for (int kh = 0; kh < 6; kh++) {
#pragma unroll 1
        for (int kw = 0; kw < 6; kw++) {
            const int tap = kh*6 + kw;
            if (tap > 0) __syncthreads();            // prior mma done
            if (kw == 5 && kh < 5) {
                // A(kh) fully consumed after this sync? No — this tap still
                // uses A(kh). Defer A reload to after this tap's mma (below).
            }
            if (tap + 1 <= 35) stageB(tap + 1, (tap + 1) & 1);
            asm volatile("cp.async.wait_group 1;");  // B(tap) + any A done
            __syncthreads();

            const unsigned bHi = sB + (unsigned)(tap & 1)*2*B_PB;
            const int arow = mbase + kw + arsel;
            const unsigned aBase = sA + (unsigned)(arow*128);
            const int axr = (arow & 7);
#pragma unroll
            for (int kf = 0; kf < 4; kf++) {
                int ac = kf*2 + acsel;
                unsigned aaddr = aBase + (unsigned)(((ac ^ axr))*16);
                uint32_t ah0,ah1,ah2,ah3, al0,al1,al2,al3;
                ldsm4(ah0, ah1, ah2, ah3, aaddr);
                ldsm4(al0, al1, al2, al3, aaddr + A_PB);
                int bc = kf*2 + bcsel;
#pragma unroll
                for (int bq = 0; bq < 4; bq++) {
                    int bro = bq*16 + brsel;
                    unsigned baddr = bHi + (unsigned)(bro*128 + ((bc ^ (bro&7))*16));
                    uint32_t bh0,bh1,bh2,bh3, bl0,bl1,bl2,bl3;
                    ldsm4(bh0, bh1, bh2, bh3, baddr);
                    ldsm4(bl0, bl1, bl2, bl3, baddr + B_PB);
                    mma16816(acc[2*bq],   ah0,ah1,ah2,ah3, bh0,bh1);
                    mma16816(acc[2*bq],   ah0,ah1,ah2,ah3, bl0,bl1);
                    mma16816(acc[2*bq],   al0,al1,al2,al3, bh0,bh1);
                    mma16816(acc[2*bq+1], ah0,ah1,ah2,ah3, bh2,bh3);
                    mma16816(acc[2*bq+1], ah0,ah1,ah2,ah3, bl2,bl3);
                    mma16816(acc[2*bq+1], al0,al1,al2,al3, bh2,bh3);
                }
            }
        }
        // reload A for next kh (single buffer): all warps finished kh's mma
        if (kh < 5) {
            __syncthreads();
            stageA(kh + 1);
        }
    }

    {
        int p0 = mbase + (lane >> 2);
        int p1 = p0 + 8;
        int wA = w0 + p0, wBp = w0 + p1;
        bool v0 = wA < W1, v1 = wBp < W1;
        float* orow = g_y2 + ((size_t)(b*CH)*H1 + h)*W1;
#pragma unroll
        for (int nt = 0; nt < 8; nt++) {
            int co = nt*8 + 2*(lane & 3);
            float bb0 = __ldg(b2 + co), bb1 = __ldg(b2 + co + 1);
            if (v0) {
                orow[(size_t)co*HWp + wA]     = fmaxf(acc[nt][0] + bb0, 0.f);
                orow[(size_t)(co+1)*HWp + wA] = fmaxf(acc[nt][1] + bb1, 0.f);
            }
            if (v1) {
                orow[(size_t)co*HWp + wBp]     = fmaxf(acc[nt][2] + bb0, 0.f);
                orow[(size_t)(co+1)*HWp + wBp] = fmaxf(acc[nt][3] + bb1, 0.f);
            }
        }
    }
}

// ---------------- conv3: 1x1, 128->64 ch, 32-cout groups ----------
__global__ void __launch_bounds__(256)
conv3_k(const float* __restrict__ w3, const float* __restrict__ b3) {
    __shared__ float ws[32*128];
    int t = threadIdx.x;
    int co0 = blockIdx.y * 32;
    for (int j = t; j < 4096; j += 256)
        ws[j] = w3[(co0 + (j >> 7))*128 + (j & 127)];
    __syncthreads();
    int p0 = blockIdx.x*1024 + t*4;
    if (p0 >= Bsz*HWp) return;
    int b = p0 / HWp, hw = p0 - b*HWp;
    const float* ih = g_h1 + (size_t)b*CHWp + hw;
    const float* iy = g_y2 + (size_t)b*CHWp + hw;
    float4 acc[32];
#pragma unroll
    for (int k = 0; k < 32; k++) {
        float bb = b3[co0+k];
        acc[k] = make_float4(bb, bb, bb, bb);
    }
#pragma unroll 2
    for (int ci = 0; ci < 64; ci++) {
        float4 xh = *(const float4*)(ih + (size_t)ci*HWp);
        float4 xy = *(const float4*)(iy + (size_t)ci*HWp);
#pragma unroll
        for (int k = 0; k < 32; k++) {
            float wh = ws[k*128 + ci], wy = ws[k*128 + 64 + ci];
            acc[k].x = fmaf(xh.x, wh, acc[k].x);
            acc[k].y = fmaf(xh.y, wh, acc[k].y);
            acc[k].z = fmaf(xh.z, wh, acc[k].z);
            acc[k].w = fmaf(xh.w, wh, acc[k].w);
            acc[k].x = fmaf(xy.x, wy, acc[k].x);
            acc[k].y = fmaf(xy.y, wy, acc[k].y);
            acc[k].z = fmaf(xy.z, wy, acc[k].z);
            acc[k].w = fmaf(xy.w, wy, acc[k].w);
        }
    }
#pragma unroll
    for (int k = 0; k < 32; k++)
        *(float4*)(g_h3 + (size_t)b*CHWp + (size_t)(co0+k)*HWp + hw) = acc[k];
}

// ---------------- primary capsules ----------
__global__ void pc_k(const float* __restrict__ pw, const float* __restrict__ pb) {
    int n = blockIdx.x*256 + threadIdx.x;
    int b = blockIdx.y;
    if (n >= Ncap) return;
    const float4* uin = (const float4*)(g_h3 + (size_t)b*CHWp + (size_t)n*8);
    float4 q0 = uin[0], q1 = uin[1];
    float ui[8] = {q0.x,q0.y,q0.z,q0.w, q1.x,q1.y,q1.z,q1.w};
    const float4* pbv = (const float4*)(pb + (size_t)n*8);
    float4 r0 = pbv[0], r1 = pbv[1];
    float a[8] = {r0.x,r0.y,r0.z,r0.w, r1.x,r1.y,r1.z,r1.w};
    const float4* pwv = (const float4*)(pw + (size_t)n*64);
#pragma unroll
    for (int i = 0; i < 8; i++) {
        float4 wA = pwv[2*i], wB = pwv[2*i+1];
        a[0] = fmaf(ui[i], wA.x, a[0]); a[1] = fmaf(ui[i], wA.y, a[1]);
        a[2] = fmaf(ui[i], wA.z, a[2]); a[3] = fmaf(ui[i], wA.w, a[3]);
        a[4] = fmaf(ui[i], wB.x, a[4]); a[5] = fmaf(ui[i], wB.y, a[5]);
        a[6] = fmaf(ui[i], wB.z, a[6]); a[7] = fmaf(ui[i], wB.w, a[7]);
    }
    float4* uo = (float4*)(g_u + ((size_t)b*Ncap + n)*8);
    uo[0] = make_float4(a[0],a[1],a[2],a[3]);
    uo[1] = make_float4(a[4],a[5],a[6],a[7]);
}

// ---- pass 0 as GEMM: s = 0.125 * sum_n u_hat (c is exactly 1/8) ----
#define S0CH 66
__global__ void __launch_bounds__(128)
s0_k(const float* __restrict__ ec) {
    __shared__ float us[S0CH*128];
    int t = threadIdx.x;
    int n0 = blockIdx.x * S0CH;
    int nEnd = n0 + S0CH; if (nEnd > Ncap) nEnd = Ncap;
    int cnt = nEnd - n0;
    for (int j = t; j < cnt*32; j += 128) {
        int nl = j >> 5, lane = j & 31;
        int bb = lane >> 1, half = lane & 1;
        *(float4*)(us + nl*128 + bb*8 + half*4) =
            *(const float4*)(g_u + ((size_t)bb*Ncap + n0 + nl)*8 + half*4);
    }
    __syncthreads();
    float acc[16];
#pragma unroll
    for (int bb = 0; bb < 16; bb++) acc[bb] = 0.f;
    const float* ep = ec + (size_t)n0*1024 + t*8;
    float4 w0 = *(const float4*)ep;
    float4 w1 = *(const float4*)(ep + 4);
    for (int nl = 0; nl < cnt; nl++) {
        float4 c0 = w0, c1 = w1;
        if (nl + 1 < cnt) {
            w0 = *(const float4*)(ep + (size_t)(nl+1)*1024);
            w1 = *(const float4*)(ep + (size_t)(nl+1)*1024 + 4);
        }
        const float* ub = us + nl*128;
#pragma unroll
        for (int bb = 0; bb < 16; bb++) {
            float4 u0 = *(const float4*)(ub + bb*8);
            float4 u1 = *(const float4*)(ub + bb*8 + 4);
            float s = c0.x*u0.x + c0.y*u0.y + c0.z*u0.z + c0.w*u0.w
                    + c1.x*u1.x + c1.y*u1.y + c1.z*u1.z + c1.w*u1.w;
            acc[bb] += s;
        }
    }
#pragma unroll
    for (int bb = 0; bb < 16; bb++)
        atomicAdd(g_s + bb*128 + t, 0.125f * acc[bb]);
}

// ---------------- routing pass (1,2): cp.async pipelined, 2-wide ILP -----
#define RGROUP 6
#define RCHUNK 66
#define ECROW 132
#define ECN (Ecls*ECROW)
#define R_SMEM_BYTES ((2*RGROUP*ECN + 2*RGROUP*128) * 4)

__device__ __forceinline__ void cpa16(unsigned d, const void* s) {
    asm volatile("cp.async.cg.shared.global [%0], [%1], 16;" :: "r"(d), "l"(s));
}
__device__ __forceinline__ float shx(float v, int m) {
    return __shfl_xor_sync(0xffffffffu, v, m);
}

__global__ void __launch_bounds__(128)
route_k(const float* __restrict__ ec, int pass) {
    extern __shared__ float rs[];
    float* ecs = rs;
    float* us  = rs + 2*RGROUP*ECN;
    int t = threadIdx.x;
    int b = t >> 3, e = t & 7;
    float* sout = g_s + pass*2048;

    float vs[16];
    const float4* vp = (const float4*)(g_vsum + t*16);
#pragma unroll
    for (int q = 0; q < 4; q++) {
        float4 v = vp[q];
        vs[q*4+0] = v.x; vs[q*4+1] = v.y; vs[q*4+2] = v.z; vs[q*4+3] = v.w;
    }
    float accs[16];
#pragma unroll
    for (int o = 0; o < 16; o++) accs[o] = 0.f;

    int n0 = blockIdx.x * RCHUNK;
    int nEnd = n0 + RCHUNK; if (nEnd > Ncap) nEnd = Ncap;
    int gTot = (nEnd - n0 + RGROUP - 1) / RGROUP;

    auto stage = [&](int g, int buf) {
        int nb = n0 + g*RGROUP;
        unsigned ecd = (unsigned)__cvta_generic_to_shared(ecs + buf*RGROUP*ECN);
        unsigned usd = (unsigned)__cvta_generic_to_shared(us  + buf*RGROUP*128);
#pragma unroll
        for (int j = 0; j < 12; j++) {
            int idx = t + j*128;
            int nl = idx >> 8, c = idx & 255;
            int n = nb + nl;
            if (n < nEnd)
                cpa16(ecd + (unsigned)(nl*ECN + (c>>5)*ECROW + (c&31)*4)*4u,
                      ec + (size_t)n*1024 + c*4);
        }
#pragma unroll
        for (int j = 0; j < 2; j++) {
            int idx = t + j*128;
            if (idx < RGROUP*32) {
                int nl = idx >> 5, lane = idx & 31;
                int n = nb + nl;
                int bb = lane >> 1, half = lane & 1;
                if (n < nEnd)
                    cpa16(usd + (unsigned)(nl*128 + bb*8 + half*4)*4u,
                          g_u + ((size_t)bb*Ncap + n)*8 + half*4);
            }
        }
        asm volatile("cp.async.commit_group;");
    };

    stage(0, 0);
    for (int g = 0; g < gTot; g++) {
        if (g + 1 < gTot) {
            stage(g+1, (g+1)&1);
            asm volatile("cp.async.wait_group 1;");
        } else {
            asm volatile("cp.async.wait_group 0;");
        }
        __syncthreads();
        int cnt = nEnd - (n0 + g*RGROUP);
        if (cnt > RGROUP) cnt = RGROUP;
        const float* eb = ecs + (g&1)*RGROUP*ECN;
        const float* ub = us  + (g&1)*RGROUP*128;
        int nl = 0;
        for (; nl + 1 < cnt; nl += 2) {
            const float* un0 = ub + nl*128 + b*8;
            float4 x0 = *(const float4*)un0;
            float4 x1 = *(const float4*)(un0 + 4);
            float4 y0 = *(const float4*)(un0 + 128);
            float4 y1 = *(const float4*)(un0 + 132);
            float ua[8] = {x0.x,x0.y,x0.z,x0.w, x1.x,x1.y,x1.z,x1.w};
            float ubv[8] = {y0.x,y0.y,y0.z,y0.w, y1.x,y1.y,y1.z,y1.w};
            const float4* ep0 = (const float4*)(eb + nl*ECN + e*ECROW);
            const float4* ep1 = (const float4*)(eb + (nl+1)*ECN + e*ECROW);
            float uh0[16], uh1[16];
            float bl0 = 0.f, bl1 = 0.f;
#pragma unroll
            for (int o = 0; o < 16; o++) {
                float4 wA = ep0[2*o], wB = ep0[2*o+1];
                float s = wA.x*ua[0] + wA.y*ua[1] + wA.z*ua[2] + wA.w*ua[3]
                        + wB.x*ua[4] + wB.y*ua[5] + wB.z*ua[6] + wB.w*ua[7];
                uh0[o] = s; bl0 = fmaf(s, vs[o], bl0);
                float4 wC = ep1[2*o], wD = ep1[2*o+1];
                float s1 = wC.x*ubv[0] + wC.y*ubv[1] + wC.z*ubv[2] + wC.w*ubv[3]
                         + wD.x*ubv[4] + wD.y*ubv[5] + wD.z*ubv[6] + wD.w*ubv[7];
                uh1[o] = s1; bl1 = fmaf(s1, vs[o], bl1);
            }
            float m0 = bl0, m1 = bl1;
            m0 = fmaxf(m0, shx(m0, 1)); m1 = fmaxf(m1, shx(m1, 1));
            m0 = fmaxf(m0, shx(m0, 2)); m1 = fmaxf(m1, shx(m1, 2));
            m0 = fmaxf(m0, shx(m0, 4)); m1 = fmaxf(m1, shx(m1, 4));
            float e0 = __expf(bl0 - m0), e1 = __expf(bl1 - m1);
            float d0 = e0, d1 = e1;
            d0 += shx(d0, 1); d1 += shx(d1, 1);
            d0 += shx(d0, 2); d1 += shx(d1, 2);
            d0 += shx(d0, 4); d1 += shx(d1, 4);
            float c0 = e0 / d0, c1 = e1 / d1;
#pragma unroll
            for (int o = 0; o < 16; o++)
                accs[o] = fmaf(c1, uh1[o], fmaf(c0, uh0[o], accs[o]));
        }
        if (nl < cnt) {
            const float* un = ub + nl*128 + b*8;
            float4 u0 = *(const float4*)un;
            float4 u1 = *(const float4*)(un + 4);
            float ua[8] = {u0.x,u0.y,u0.z,u0.w, u1.x,u1.y,u1.z,u1.w};
            const float4* ep = (const float4*)(eb + nl*ECN + e*ECROW);
            float uh[16];
            float bl = 0.f;
#pragma unroll
            for (int o = 0; o < 16; o++) {
                float4 wA = ep[2*o], wB = ep[2*o+1];
                float s = wA.x*ua[0] + wA.y*ua[1] + wA.z*ua[2] + wA.w*ua[3]
                        + wB.x*ua[4] + wB.y*ua[5] + wB.z*ua[6] + wB.w*ua[7];
                uh[o] = s;
                bl = fmaf(s, vs[o], bl);
            }
            float m = bl;
            m = fmaxf(m, shx(m, 1));
            m = fmaxf(m, shx(m, 2));
            m = fmaxf(m, shx(m, 4));
            float ex = __expf(bl - m);
            float den = ex;
            den += shx(den, 1);
            den += shx(den, 2);
            den += shx(den, 4);
            float c = ex / den;
#pragma unroll
            for (int o = 0; o < 16; o++) accs[o] = fmaf(c, uh[o], accs[o]);
        }
        __syncthreads();
    }
#pragma unroll
    for (int o = 0; o < 16; o++) atomicAdd(sout + t*16 + o, accs[o]);
}

// ---------------- squash + accumulate vsum ----------------
__global__ void squash_k(int pass) {
    int t = threadIdx.x;
    const float* sp = g_s + pass*2048 + t*16;
    float sv[16]; float nn = 0.f;
#pragma unroll
    for (int o = 0; o < 16; o++) { sv[o] = sp[o]; nn = fmaf(sv[o], sv[o], nn); }
    float nrm = sqrtf(nn);
    float sc = nn / (1.f + nn) / (nrm + 1e-8f);
#pragma unroll
    for (int o = 0; o < 16; o++) g_vsum[t*16 + o] += sc * sv[o];
}

__global__ void final_k(float* __restrict__ out) {
    int t = threadIdx.x;
    const float* sp = g_s + 2*2048 + t*16;
    float nn = 0.f;
#pragma unroll
    for (int o = 0; o < 16; o++) { float v = sp[o]; nn = fmaf(v, v, nn); }
    float nrm = sqrtf(nn);
    float sc = nn / (1.f + nn) / (nrm + 1e-8f);
    out[t] = sc * nrm;
}

// ---------------- launch ----------------
extern "C" void kernel_launch(void* const* d_in, const int* in_sizes, int n_in,
                              void* d_out, int out_size) {
    const float* x  = (const float*)d_in[0];
    const float* w1 = (const float*)d_in[1];
    const float* b1 = (const float*)d_in[2];
    const float* w2 = (const float*)d_in[3];
    const float* b2 = (const float*)d_in[4];
    const float* w3 = (const float*)d_in[5];
    const float* b3 = (const float*)d_in[6];
    const float* pw = (const float*)d_in[7];
    const float* pb = (const float*)d_in[8];
    const float* ec = (const float*)d_in[9];
    float* out = (float*)d_out;

    cudaFuncSetAttribute(conv1_k, cudaFuncAttributeMaxDynamicSharedMemorySize,
                         C1_SMEM);
    cudaFuncSetAttribute(conv2_mma, cudaFuncAttributeMaxDynamicSharedMemorySize,
                         C2_SMEM);
    cudaFuncSetAttribute(route_k, cudaFuncAttributeMaxDynamicSharedMemorySize,
                         R_SMEM_BYTES);

    zero_k<<<24, 256>>>();
    zerop_k<<<(16*1460*8 + 255)/256, 256>>>();
    splitw2_k<<<(64*2304 + 255)/256, 256>>>(w2);
    conv1_k<<<dim3(7, Bsz), 512, C1_SMEM>>>(x, w1, b1);
    conv2_mma<<<dim3(2, H1, Bsz), 256, C2_SMEM>>>(b2);
    conv3_k<<<dim3(56, 2), 256>>>(w3, b3);
    pc_k<<<dim3((Ncap + 255)/256, Bsz), 256>>>(pw, pb);

    int rblocks = (Ncap + RCHUNK - 1) / RCHUNK;
    s0_k<<<(Ncap + S0CH - 1)/S0CH, 128>>>(ec);
    squash_k<<<1, 128>>>(0);
    route_k<<<rblocks, 128, R_SMEM_BYTES>>>(ec, 1);
    squash_k<<<1, 128>>>(1);
    route_k<<<rblocks, 128, R_SMEM_BYTES>>>(ec, 2);
    final_k<<<1, 128>>>(out);
}

// round 17
// speedup vs baseline: 1.4311x; 1.2682x over previous
#include <cuda_runtime.h>
#include <cuda_bf16.h>
#include <math.h>
#include <stdint.h>

// Shapes
#define Bsz 16
#define CH 64
#define H1 14
#define W1 254
#define HWp (H1*W1)            // 3556
#define CHWp (CH*HWp)          // 227584
#define Ncap 28448
#define Ecls 8
#define ODv 16

// padded NHWC planes for conv2 A operand
#define PRows 19
#define PCols 264
#define PLANE_E ((size_t)Bsz*PRows*PCols*64)

// ---------------- scratch ----------------
__device__ float g_h1[Bsz*CHWp];
__device__ float g_y2[Bsz*CHWp];
__device__ float g_h3[Bsz*CHWp];
__device__ float g_u [Bsz*Ncap*8];
__device__ float g_s [3*2048];
__device__ float g_vsum[2048];
__device__ __nv_bfloat16 g_h1h[PLANE_E];
__device__ __nv_bfloat16 g_h1l[PLANE_E];
__device__ __nv_bfloat16 g_w2t[36*2*4096];           // [tap][hl][co][ci]
__device__ __nv_bfloat16 g_ech[(size_t)Ncap*1024];   // [n][eo][i] hi
__device__ __nv_bfloat16 g_ecl[(size_t)Ncap*1024];   // lo
__device__ __nv_bfloat16 g_u16h[(size_t)Ncap*16*8];  // [n][b][i] hi
__device__ __nv_bfloat16 g_u16l[(size_t)Ncap*16*8];  // lo

__global__ void zero_k() {
    int t = blockIdx.x*256 + threadIdx.x;
    if (t < 3*2048) g_s[t] = 0.f;
    if (t < 2048)   g_vsum[t] = 0.f;
}
__global__ void zerop_k() {
    int i = blockIdx.x*256 + threadIdx.x;
    if (i >= 16*1460*8) return;
    int c8 = i & 7; int r = i >> 3;
    int b = r / 1460; int p = r - b*1460;
    int row, col;
    if (p < 1320) { int rr = p/264; col = p - rr*264; row = rr < 2 ? rr : rr + 14; }
    else { int q = p - 1320; int rr = q/10; int cc = q - rr*10;
           row = 2 + rr; col = cc < 2 ? cc : cc + 254; }
    size_t off = (((size_t)b*PRows + row)*PCols + col)*64 + c8*8;
    uint4 z = make_uint4(0,0,0,0);
    *(uint4*)(g_h1h + off) = z;
    *(uint4*)(g_h1l + off) = z;
}

// ---------------- prep: transpose+split w2 ----------------
__global__ void splitw2_k(const float* __restrict__ w2) {
    int i = blockIdx.x*256 + threadIdx.x;
    if (i < 64*2304) {
        int co = i / 2304, r = i - co*2304;
        int ci = r / 36, tap = r - ci*36;
        float v = w2[i];
        __nv_bfloat16 h = __float2bfloat16(v);
        __nv_bfloat16 l = __float2bfloat16(v - __bfloat162float(h));
        g_w2t[(tap*2+0)*4096 + co*64 + ci] = h;
        g_w2t[(tap*2+1)*4096 + co*64 + ci] = l;
    }
}
// ---------------- prep: split ec into bf16 hi/lo planes ----------------
__global__ void splitec_k(const float* __restrict__ ec) {
    size_t i = ((size_t)blockIdx.x*256 + threadIdx.x)*8;
    if (i >= (size_t)Ncap*1024) return;
    float4 a = *(const float4*)(ec + i);
    float4 b = *(const float4*)(ec + i + 4);
    __nv_bfloat162 h0 = __floats2bfloat162_rn(a.x, a.y);
    __nv_bfloat162 h1 = __floats2bfloat162_rn(a.z, a.w);
    __nv_bfloat162 h2 = __floats2bfloat162_rn(b.x, b.y);
    __nv_bfloat162 h3 = __floats2bfloat162_rn(b.z, b.w);
    __nv_bfloat162 l0 = __floats2bfloat162_rn(a.x-__bfloat162float(h0.x), a.y-__bfloat162float(h0.y));
    __nv_bfloat162 l1 = __floats2bfloat162_rn(a.z-__bfloat162float(h1.x), a.w-__bfloat162float(h1.y));
    __nv_bfloat162 l2 = __floats2bfloat162_rn(b.x-__bfloat162float(h2.x), b.y-__bfloat162float(h2.y));
    __nv_bfloat162 l3 = __floats2bfloat162_rn(b.z-__bfloat162float(h3.x), b.w-__bfloat162float(h3.y));
    *(uint4*)(g_ech + i) = make_uint4(*(uint32_t*)&h0, *(uint32_t*)&h1,
                                      *(uint32_t*)&h2, *(uint32_t*)&h3);
    *(uint4*)(g_ecl + i) = make_uint4(*(uint32_t*)&l0, *(uint32_t*)&l1,
                                      *(uint32_t*)&l2, *(uint32_t*)&l3);
}

// ---- conv1: 1->64ch 6x6 s2, relu; fp32 + NHWC bf16 hi/lo via smem transpose --
#define C1_SMEM ((4096+2304+64)*4 + 512*17*4)
__global__ void __launch_bounds__(512)
conv1_k(const float* __restrict__ x,
        const float* __restrict__ w1,
        const float* __restrict__ b1) {
    extern __shared__ float c1s[];
    float* xs = c1s;
    float* ws = xs + 4096;
    float* bs = ws + 2304;
    uint32_t* buf = (uint32_t*)(bs + 64);
    int h2 = blockIdx.x, b = blockIdx.y, t = threadIdx.x;
    const float* xrow = x + b*(32*512) + (4*h2)*512;
    for (int j = t; j < 4096; j += 512) xs[j] = xrow[j];
    for (int j = t; j < 2304; j += 512) ws[j] = w1[j];
    if (t < 64) bs[t] = b1[t];
    __syncthreads();
    int sub = t >> 8, tw = t & 255;
    bool val = tw < W1;
    int twc = val ? tw : 0;
    float win[36];
#pragma unroll
    for (int r = 0; r < 6; r++)
#pragma unroll
        for (int k = 0; k < 6; k++) win[r*6+k] = xs[(sub*2 + r)*512 + 2*twc + k];
    float* outp = g_h1 + (size_t)(b*CH*H1 + h2*2 + sub)*W1 + twc;
    for (int g = 0; g < 4; g++) {
#pragma unroll
        for (int fp = 0; fp < 8; fp++) {
            int f = g*16 + fp*2;
            float a0 = bs[f], a1 = bs[f+1];
            const float* wp0 = ws + f*36;
            const float* wp1 = wp0 + 36;
#pragma unroll
            for (int k = 0; k < 36; k++) {
                a0 = fmaf(win[k], wp0[k], a0);
                a1 = fmaf(win[k], wp1[k], a1);
            }
            a0 = fmaxf(a0, 0.f); a1 = fmaxf(a1, 0.f);
            if (val) {
                outp[(size_t)f*HWp]     = a0;
                outp[(size_t)(f+1)*HWp] = a1;
            }
            __nv_bfloat162 hv = __floats2bfloat162_rn(a0, a1);
            __nv_bfloat162 lv = __floats2bfloat162_rn(
                a0 - __bfloat162float(hv.x), a1 - __bfloat162float(hv.y));
            buf[t*17 + fp]     = *(uint32_t*)&hv;
            buf[t*17 + 8 + fp] = *(uint32_t*)&lv;
        }
        __syncthreads();
#pragma unroll
        for (int i = 0; i < 4; i++) {
            int j = t + i*512;
            int pos = j >> 2, q = j & 3;
            int psub = pos >> 8, ptw = pos & 255;
            if (ptw < W1) {
                const uint32_t* src = buf + pos*17 + (q >> 1)*8 + (q & 1)*4;
                uint4 v = make_uint4(src[0], src[1], src[2], src[3]);
                size_t boff = ((((size_t)b*PRows + h2*2 + psub + 2)*PCols + ptw + 2)*64
                               + g*16)*2 + (q & 1)*16;
                char* base = (char*)((q < 2) ? g_h1h : g_h1l);
                *(uint4*)(base + boff) = v;
            }
        }
        __syncthreads();
    }
}

// ===== conv2: tap-decomposed GEMM; single A, double B; 3 CTA/SM ====
#define AROWS 134
#define A_PB (AROWS*128)
#define B_PB (64*128)
#define C2S_A (2*A_PB)
#define C2S_B (4*B_PB)
#define C2_SMEM (C2S_A + C2S_B)

static __device__ __forceinline__ void mma16816(float* c,
    uint32_t a0, uint32_t a1, uint32_t a2, uint32_t a3,
    uint32_t b0, uint32_t b1) {
    asm volatile(
        "mma.sync.aligned.m16n8k16.row.col.f32.bf16.bf16.f32 "
        "{%0,%1,%2,%3}, {%4,%5,%6,%7}, {%8,%9}, {%0,%1,%2,%3};"
        : "+f"(c[0]), "+f"(c[1]), "+f"(c[2]), "+f"(c[3])
        : "r"(a0), "r"(a1), "r"(a2), "r"(a3), "r"(b0), "r"(b1));
}
static __device__ __forceinline__ void ldsm4(uint32_t& r0, uint32_t& r1,
    uint32_t& r2, uint32_t& r3, unsigned a) {
    asm volatile("ldmatrix.sync.aligned.m8n8.x4.shared.b16 {%0,%1,%2,%3}, [%4];"
        : "=r"(r0), "=r"(r1), "=r"(r2), "=r"(r3) : "r"(a));
}
__device__ __forceinline__ void cpa16(unsigned d, const void* s) {
    asm volatile("cp.async.cg.shared.global [%0], [%1], 16;" :: "r"(d), "l"(s));
}
__device__ __forceinline__ float shx(float v, int m) {
    return __shfl_xor_sync(0xffffffffu, v, m);
}

__global__ void __launch_bounds__(256, 3)
conv2_mma(const float* __restrict__ b2) {
    extern __shared__ char cs2[];
    unsigned sA, sB;
    { unsigned u; asm("{ .reg .u64 tp; cvta.to.shared.u64 tp, %1; cvt.u32.u64 %0, tp; }"
                      : "=r"(u) : "l"(cs2));
      sA = u; sB = u + C2S_A; }

    const int wt = blockIdx.x, h = blockIdx.y, b = blockIdx.z;
    const int t = threadIdx.x, lane = t & 31, wid = t >> 5;
    const int mbase = wid * 16;
    const int w0 = wt * 128;

    float acc[8][4];
#pragma unroll
    for (int nt = 0; nt < 8; nt++)
#pragma unroll
        for (int q = 0; q < 4; q++) acc[nt][q] = 0.f;

    auto stageA = [&](int kh) {
        const char* ph = (const char*)(g_h1h + (((size_t)b*PRows + h+kh)*PCols + w0)*64);
        const char* pl = (const char*)(g_h1l + (((size_t)b*PRows + h+kh)*PCols + w0)*64);
#pragma unroll
        for (int i = 0; i < 9; i++) {
            int idx = t + i*256;
            if (idx < 2144) {
                int hl = idx >= 1072;
                int r = idx - hl*1072;
                int pp = r >> 3, c = r & 7;
                cpa16(sA + (unsigned)(hl*A_PB + pp*128 + ((c^(pp&7))*16)),
                      (hl ? pl : ph) + pp*128 + c*16);
            }
        }
        asm volatile("cp.async.commit_group;");
    };
    auto stageB = [&](int tap, int buf) {
#pragma unroll
        for (int i = 0; i < 4; i++) {
            int idx = t + i*256;
            int hl = idx >> 9;
            int r = idx & 511;
            int co = r >> 3, c = r & 7;
            cpa16(sB + (unsigned)((buf*2+hl)*B_PB + co*128 + ((c^(co&7))*16)),
                  (const char*)(g_w2t + (size_t)(tap*2+hl)*4096 + co*64) + c*16);
        }
        asm volatile("cp.async.commit_group;");
    };

    stageB(0, 0);
    stageA(0);
    asm volatile("cp.async.wait_group 0;");
    __syncthreads();

    const int arsel = (lane & 7) + ((lane >> 3) & 1)*8;
    const int acsel = (lane >> 4) & 1;
    const int brsel = (lane & 7) + ((lane >> 4) & 1)*8;
    const int bcsel = (lane >> 3) & 1;

    for (int kh = 0; kh < 6; kh++) {
#pragma unroll 1
        for (int kw = 0; kw < 6; kw++) {
            const int tap = kh*6 + kw;
            if (tap > 0) __syncthreads();
            if (tap + 1 <= 35) stageB(tap + 1, (tap + 1) & 1);
            asm volatile("cp.async.wait_group 1;");
            __syncthreads();

            const unsigned bHi = sB + (unsigned)(tap & 1)*2*B_PB;
            const int arow = mbase + kw + arsel;
            const unsigned aBase = sA + (unsigned)(arow*128);
            const int axr = (arow & 7);
#pragma unroll
            for (int kf = 0; kf < 4; kf++) {
                int ac = kf*2 + acsel;
                unsigned aaddr = aBase + (unsigned)(((ac ^ axr))*16);
                uint32_t ah0,ah1,ah2,ah3, al0,al1,al2,al3;
                ldsm4(ah0, ah1, ah2, ah3, aaddr);
                ldsm4(al0, al1, al2, al3, aaddr + A_PB);
                int bc = kf*2 + bcsel;
#pragma unroll
                for (int bq = 0; bq < 4; bq++) {
                    int bro = bq*16 + brsel;
                    unsigned baddr = bHi + (unsigned)(bro*128 + ((bc ^ (bro&7))*16));
                    uint32_t bh0,bh1,bh2,bh3, bl0,bl1,bl2,bl3;
                    ldsm4(bh0, bh1, bh2, bh3, baddr);
                    ldsm4(bl0, bl1, bl2, bl3, baddr + B_PB);
                    mma16816(acc[2*bq],   ah0,ah1,ah2,ah3, bh0,bh1);
                    mma16816(acc[2*bq],   ah0,ah1,ah2,ah3, bl0,bl1);
                    mma16816(acc[2*bq],   al0,al1,al2,al3, bh0,bh1);
                    mma16816(acc[2*bq+1], ah0,ah1,ah2,ah3, bh2,bh3);
                    mma16816(acc[2*bq+1], ah0,ah1,ah2,ah3, bl2,bl3);
                    mma16816(acc[2*bq+1], al0,al1,al2,al3, bh2,bh3);
                }
            }
        }
        if (kh < 5) {
            __syncthreads();
            stageA(kh + 1);
        }
    }

    {
        int p0 = mbase + (lane >> 2);
        int p1 = p0 + 8;
        int wA = w0 + p0, wBp = w0 + p1;
        bool v0 = wA < W1, v1 = wBp < W1;
        float* orow = g_y2 + ((size_t)(b*CH)*H1 + h)*W1;
#pragma unroll
        for (int nt = 0; nt < 8; nt++) {
            int co = nt*8 + 2*(lane & 3);
            float bb0 = __ldg(b2 + co), bb1 = __ldg(b2 + co + 1);
            if (v0) {
                orow[(size_t)co*HWp + wA]     = fmaxf(acc[nt][0] + bb0, 0.f);
                orow[(size_t)(co+1)*HWp + wA] = fmaxf(acc[nt][1] + bb1, 0.f);
            }
            if (v1) {
                orow[(size_t)co*HWp + wBp]     = fmaxf(acc[nt][2] + bb0, 0.f);
                orow[(size_t)(co+1)*HWp + wBp] = fmaxf(acc[nt][3] + bb1, 0.f);
            }
        }
    }
}

// ---------------- conv3: 1x1, 128->64 ch, 32-cout groups ----------
__global__ void __launch_bounds__(256)
conv3_k(const float* __restrict__ w3, const float* __restrict__ b3) {
    __shared__ float ws[32*128];
    int t = threadIdx.x;
    int co0 = blockIdx.y * 32;
    for (int j = t; j < 4096; j += 256)
        ws[j] = w3[(co0 + (j >> 7))*128 + (j & 127)];
    __syncthreads();
    int p0 = blockIdx.x*1024 + t*4;
    if (p0 >= Bsz*HWp) return;
    int b = p0 / HWp, hw = p0 - b*HWp;
    const float* ih = g_h1 + (size_t)b*CHWp + hw;
    const float* iy = g_y2 + (size_t)b*CHWp + hw;
    float4 acc[32];
#pragma unroll
    for (int k = 0; k < 32; k++) {
        float bb = b3[co0+k];
        acc[k] = make_float4(bb, bb, bb, bb);
    }
#pragma unroll 2
    for (int ci = 0; ci < 64; ci++) {
        float4 xh = *(const float4*)(ih + (size_t)ci*HWp);
        float4 xy = *(const float4*)(iy + (size_t)ci*HWp);
#pragma unroll
        for (int k = 0; k < 32; k++) {
            float wh = ws[k*128 + ci], wy = ws[k*128 + 64 + ci];
            acc[k].x = fmaf(xh.x, wh, acc[k].x);
            acc[k].y = fmaf(xh.y, wh, acc[k].y);
            acc[k].z = fmaf(xh.z, wh, acc[k].z);
            acc[k].w = fmaf(xh.w, wh, acc[k].w);
            acc[k].x = fmaf(xy.x, wy, acc[k].x);
            acc[k].y = fmaf(xy.y, wy, acc[k].y);
            acc[k].z = fmaf(xy.z, wy, acc[k].z);
            acc[k].w = fmaf(xy.w, wy, acc[k].w);
        }
    }
#pragma unroll
    for (int k = 0; k < 32; k++)
        *(float4*)(g_h3 + (size_t)b*CHWp + (size_t)(co0+k)*HWp + hw) = acc[k];
}

// ---------------- primary capsules (+ bf16 hi/lo u for routing) ----------
__global__ void pc_k(const float* __restrict__ pw, const float* __restrict__ pb) {
    int n = blockIdx.x*256 + threadIdx.x;
    int b = blockIdx.y;
    if (n >= Ncap) return;
    const float4* uin = (const float4*)(g_h3 + (size_t)b*CHWp + (size_t)n*8);
    float4 q0 = uin[0], q1 = uin[1];
    float ui[8] = {q0.x,q0.y,q0.z,q0.w, q1.x,q1.y,q1.z,q1.w};
    const float4* pbv = (const float4*)(pb + (size_t)n*8);
    float4 r0 = pbv[0], r1 = pbv[1];
    float a[8] = {r0.x,r0.y,r0.z,r0.w, r1.x,r1.y,r1.z,r1.w};
    const float4* pwv = (const float4*)(pw + (size_t)n*64);
#pragma unroll
    for (int i = 0; i < 8; i++) {
        float4 wA = pwv[2*i], wB = pwv[2*i+1];
        a[0] = fmaf(ui[i], wA.x, a[0]); a[1] = fmaf(ui[i], wA.y, a[1]);
        a[2] = fmaf(ui[i], wA.z, a[2]); a[3] = fmaf(ui[i], wA.w, a[3]);
        a[4] = fmaf(ui[i], wB.x, a[4]); a[5] = fmaf(ui[i], wB.y, a[5]);
        a[6] = fmaf(ui[i], wB.z, a[6]); a[7] = fmaf(ui[i], wB.w, a[7]);
    }
    float4* uo = (float4*)(g_u + ((size_t)b*Ncap + n)*8);
    uo[0] = make_float4(a[0],a[1],a[2],a[3]);
    uo[1] = make_float4(a[4],a[5],a[6],a[7]);
    // bf16 hi/lo planes, layout [n][b][8i]
    uint32_t hw_[4], lw_[4];
#pragma unroll
    for (int q = 0; q < 4; q++) {
        __nv_bfloat162 hv = __floats2bfloat162_rn(a[2*q], a[2*q+1]);
        __nv_bfloat162 lv = __floats2bfloat162_rn(
            a[2*q] - __bfloat162float(hv.x), a[2*q+1] - __bfloat162float(hv.y));
        hw_[q] = *(uint32_t*)&hv; lw_[q] = *(uint32_t*)&lv;
    }
    *(uint4*)(g_u16h + ((size_t)n*16 + b)*8) = make_uint4(hw_[0],hw_[1],hw_[2],hw_[3]);
    *(uint4*)(g_u16l + ((size_t)n*16 + b)*8) = make_uint4(lw_[0],lw_[1],lw_[2],lw_[3]);
}

// ---- pass 0 as GEMM: s = 0.125 * sum_n u_hat (c is exactly 1/8) ----
#define S0CH 66
__global__ void __launch_bounds__(128)
s0_k(const float* __restrict__ ec) {
    __shared__ float us[S0CH*128];
    int t = threadIdx.x;
    int n0 = blockIdx.x * S0CH;
    int nEnd = n0 + S0CH; if (nEnd > Ncap) nEnd = Ncap;
    int cnt = nEnd - n0;
    for (int j = t; j < cnt*32; j += 128) {
        int nl = j >> 5, lane = j & 31;
        int bb = lane >> 1, half = lane & 1;
        *(float4*)(us + nl*128 + bb*8 + half*4) =
            *(const float4*)(g_u + ((size_t)bb*Ncap + n0 + nl)*8 + half*4);
    }
    __syncthreads();
    float acc[16];
#pragma unroll
    for (int bb = 0; bb < 16; bb++) acc[bb] = 0.f;
    const float* ep = ec + (size_t)n0*1024 + t*8;
    float4 w0 = *(const float4*)ep;
    float4 w1 = *(const float4*)(ep + 4);
    for (int nl = 0; nl < cnt; nl++) {
        float4 c0 = w0, c1 = w1;
        if (nl + 1 < cnt) {
            w0 = *(const float4*)(ep + (size_t)(nl+1)*1024);
            w1 = *(const float4*)(ep + (size_t)(nl+1)*1024 + 4);
        }
        const float* ub = us + nl*128;
#pragma unroll
        for (int bb = 0; bb < 16; bb++) {
            float4 u0 = *(const float4*)(ub + bb*8);
            float4 u1 = *(const float4*)(ub + bb*8 + 4);
            float s = c0.x*u0.x + c0.y*u0.y + c0.z*u0.z + c0.w*u0.w
                    + c1.x*u1.x + c1.y*u1.y + c1.z*u1.z + c1.w*u1.w;
            acc[bb] += s;
        }
    }
#pragma unroll
    for (int bb = 0; bb < 16; bb++)
        atomicAdd(g_s + bb*128 + t, 0.125f * acc[bb]);
}

// ======== routing passes 1,2 via HMMA: one warp per capsule ========
// u_hat[16b][128eo] = U[16x8] . EC[128x8]^T, 3-term bf16 in 2 mma/tile.
#define RV2_SLOT 4608                     // Bh 2048 | Bl 2048 | Ah 256 | Al 256
#define RV2_STAGE (8*2*RV2_SLOT)          // 73728
#define RV2_SMEM (RV2_STAGE + 8704)       // + skewed vs[16][136]

__global__ void __launch_bounds__(256, 1)
route2_k(int pass) {
    extern __shared__ char rsm[];
    float* vss = (float*)(rsm + RV2_STAGE);
    const int t = threadIdx.x, lane = t & 31, wid = t >> 5;
    unsigned sb;
    asm("{ .reg .u64 tp; cvta.to.shared.u64 tp, %1; cvt.u32.u64 %0, tp; }"
        : "=r"(sb) : "l"(rsm));
    for (int j = t; j < 2048; j += 256)
        vss[(j >> 7)*136 + (j & 127)] = g_vsum[j];
    __syncthreads();

    const unsigned slot0 = sb + wid*2*RV2_SLOT;
    const int wg = blockIdx.x*8 + wid;    // grid must be 148 -> 1184 warps
    const int NW = 1184;

    auto stage = [&](int n, int buf) {
        if (n < Ncap) {
            unsigned base = slot0 + buf*RV2_SLOT;
            const __nv_bfloat16* eh = g_ech + (size_t)n*1024;
            const __nv_bfloat16* el = g_ecl + (size_t)n*1024;
#pragma unroll
            for (int q = 0; q < 4; q++) {
                int ch = lane + q*32;
                cpa16(base + (unsigned)ch*16, eh + ch*8);
                cpa16(base + 2048u + (unsigned)ch*16, el + ch*8);
            }
            if (lane < 16)
                cpa16(base + 4096u + (unsigned)lane*16,
                      g_u16h + ((size_t)n*16 + lane)*8);
            else
                cpa16(base + 4352u + (unsigned)(lane-16)*16,
                      g_u16l + ((size_t)n*16 + lane-16)*8);
        }
        asm volatile("cp.async.commit_group;");
    };

    float accs[16][4];
#pragma unroll
    for (int T = 0; T < 16; T++)
#pragma unroll
        for (int j = 0; j < 4; j++) accs[T][j] = 0.f;

    const int r0 = lane >> 2;
    const int c0 = (lane & 3)*2;
    const unsigned aoff = 4096u + ((lane>>3)&1)*128 + ((lane>>4)&1)*256 + (lane&7)*16;
    const unsigned boff = (unsigned)((lane>>3)*128 + (lane&7)*16);

    int NK = (Ncap - 1 - wg)/NW + 1;
    stage(wg, 0);
    for (int k = 0; k < NK; k++) {
        if (k+1 < NK) {
            stage(wg + (k+1)*NW, (k+1)&1);
            asm volatile("cp.async.wait_group 1;");
        } else {
            asm volatile("cp.async.wait_group 0;");
        }
        __syncwarp();
        unsigned base = slot0 + (unsigned)(k&1)*RV2_SLOT;

        uint32_t ah0,ah1,al0,al1;
        ldsm4(ah0, ah1, al0, al1, base + aoff);
        float d[16][4];
#pragma unroll
        for (int T = 0; T < 16; T++)
#pragma unroll
            for (int j = 0; j < 4; j++) d[T][j] = 0.f;
        uint32_t zr = 0;
#pragma unroll
        for (int q = 0; q < 4; q++) {
            uint32_t bh0,bh1,bh2,bh3, bl0,bl1,bl2,bl3;
            ldsm4(bh0, bh1, bh2, bh3, base + (unsigned)q*512 + boff);
            ldsm4(bl0, bl1, bl2, bl3, base + 2048u + (unsigned)q*512 + boff);
            mma16816(d[q*4+0], ah0,ah1,al0,al1, bh0, bh0);
            mma16816(d[q*4+0], ah0,ah1,al0,al1, bl0, zr);
            mma16816(d[q*4+1], ah0,ah1,al0,al1, bh1, bh1);
            mma16816(d[q*4+1], ah0,ah1,al0,al1, bl1, zr);
            mma16816(d[q*4+2], ah0,ah1,al0,al1, bh2, bh2);
            mma16816(d[q*4+2], ah0,ah1,al0,al1, bl2, zr);
            mma16816(d[q*4+3], ah0,ah1,al0,al1, bh3, bh3);
            mma16816(d[q*4+3], ah0,ah1,al0,al1, bl3, zr);
        }
        // bl[b,e] partials + quad reduce
        float bl0a[8], bl1a[8];
#pragma unroll
        for (int e = 0; e < 8; e++) {
            const float* v0 = vss + r0*136 + e*16;
            const float* v1 = v0 + 8*136;
            int t0 = 2*e, t1 = 2*e+1;
            float p0 = d[t0][0]*v0[c0] + d[t0][1]*v0[c0+1]
                     + d[t1][0]*v0[8+c0] + d[t1][1]*v0[9+c0];
            float p1 = d[t0][2]*v1[c0] + d[t0][3]*v1[c0+1]
                     + d[t1][2]*v1[8+c0] + d[t1][3]*v1[9+c0];
            p0 += shx(p0, 1); p0 += shx(p0, 2);
            p1 += shx(p1, 1); p1 += shx(p1, 2);
            bl0a[e] = p0; bl1a[e] = p1;
        }
        // in-register softmax over e (both rows)
        float m0 = bl0a[0], m1 = bl1a[0];
#pragma unroll
        for (int e = 1; e < 8; e++) { m0 = fmaxf(m0, bl0a[e]); m1 = fmaxf(m1, bl1a[e]); }
        float c0e[8], c1e[8];
        float s0s = 0.f, s1s = 0.f;
#pragma unroll
        for (int e = 0; e < 8; e++) {
            c0e[e] = __expf(bl0a[e] - m0); s0s += c0e[e];
            c1e[e] = __expf(bl1a[e] - m1); s1s += c1e[e];
        }
        float i0 = 1.f/s0s, i1 = 1.f/s1s;
#pragma unroll
        for (int T = 0; T < 16; T++) {
            float w0c = c0e[T>>1]*i0, w1c = c1e[T>>1]*i1;
            accs[T][0] = fmaf(w0c, d[T][0], accs[T][0]);
            accs[T][1] = fmaf(w0c, d[T][1], accs[T][1]);
            accs[T][2] = fmaf(w1c, d[T][2], accs[T][2]);
            accs[T][3] = fmaf(w1c, d[T][3], accs[T][3]);
        }
    }
    // block-wide reduction of accs -> g_s
    __syncthreads();               // staging dead everywhere
    float* reg = (float*)(rsm + wid*8704);
#pragma unroll
    for (int T = 0; T < 16; T++) {
        int e = T >> 1, ob = (T&1)*8 + c0;
        reg[r0*136 + e*16 + ob]         = accs[T][0];
        reg[r0*136 + e*16 + ob + 1]     = accs[T][1];
        reg[(r0+8)*136 + e*16 + ob]     = accs[T][2];
        reg[(r0+8)*136 + e*16 + ob + 1] = accs[T][3];
    }
    __syncthreads();
    float* sout = g_s + pass*2048;
    for (int f = t; f < 2048; f += 256) {
        int r = f >> 7, c = f & 127;
        float s = 0.f;
#pragma unroll
        for (int w = 0; w < 8; w++)
            s += ((float*)(rsm + w*8704))[r*136 + c];
        atomicAdd(sout + f, s);
    }
}

// ---------------- squash + accumulate vsum ----------------
__global__ void squash_k(int pass) {
    int t = threadIdx.x;
    const float* sp = g_s + pass*2048 + t*16;
    float sv[16]; float nn = 0.f;
#pragma unroll
    for (int o = 0; o < 16; o++) { sv[o] = sp[o]; nn = fmaf(sv[o], sv[o], nn); }
    float nrm = sqrtf(nn);
    float sc = nn / (1.f + nn) / (nrm + 1e-8f);
#pragma unroll
    for (int o = 0; o < 16; o++) g_vsum[t*16 + o] += sc * sv[o];
}

__global__ void final_k(float* __restrict__ out) {
    int t = threadIdx.x;
    const float* sp = g_s + 2*2048 + t*16;
    float nn = 0.f;
#pragma unroll
    for (int o = 0; o < 16; o++) { float v = sp[o]; nn = fmaf(v, v, nn); }
    float nrm = sqrtf(nn);
    float sc = nn / (1.f + nn) / (nrm + 1e-8f);
    out[t] = sc * nrm;
}

// ---------------- launch ----------------
extern "C" void kernel_launch(void* const* d_in, const int* in_sizes, int n_in,
                              void* d_out, int out_size) {
    const float* x  = (const float*)d_in[0];
    const float* w1 = (const float*)d_in[1];
    const float* b1 = (const float*)d_in[2];
    const float* w2 = (const float*)d_in[3];
    const float* b2 = (const float*)d_in[4];
    const float* w3 = (const float*)d_in[5];
    const float* b3 = (const float*)d_in[6];
    const float* pw = (const float*)d_in[7];
    const float* pb = (const float*)d_in[8];
    const float* ec = (const float*)d_in[9];
    float* out = (float*)d_out;

    cudaFuncSetAttribute(conv1_k, cudaFuncAttributeMaxDynamicSharedMemorySize,
                         C1_SMEM);
    cudaFuncSetAttribute(conv2_mma, cudaFuncAttributeMaxDynamicSharedMemorySize,
                         C2_SMEM);
    cudaFuncSetAttribute(route2_k, cudaFuncAttributeMaxDynamicSharedMemorySize,
                         RV2_SMEM);

    zero_k<<<24, 256>>>();
    zerop_k<<<(16*1460*8 + 255)/256, 256>>>();
    splitw2_k<<<(64*2304 + 255)/256, 256>>>(w2);
    splitec_k<<<(int)(((size_t)Ncap*1024/8 + 255)/256), 256>>>(ec);
    conv1_k<<<dim3(7, Bsz), 512, C1_SMEM>>>(x, w1, b1);
    conv2_mma<<<dim3(2, H1, Bsz), 256, C2_SMEM>>>(b2);
    conv3_k<<<dim3(56, 2), 256>>>(w3, b3);
    pc_k<<<dim3((Ncap + 255)/256, Bsz), 256>>>(pw, pb);

    s0_k<<<(Ncap + S0CH - 1)/S0CH, 128>>>(ec);
    squash_k<<<1, 128>>>(0);
    route2_k<<<148, 256, RV2_SMEM>>>(1);
    squash_k<<<1, 128>>>(1);
    route2_k<<<148, 256, RV2_SMEM>>>(2);
    final_k<<<1, 128>>>(out);
}